// round 2
// baseline (speedup 1.0000x reference)
#include <cuda_runtime.h>
#include <math.h>

// ---------------------------------------------------------------------------
// MLA prefill: B=2, S=2048, D=2048, H=16, dh=128
// out = attention(RoPE(LN(x@Wdq)@Wuq), RoPE(K), V) @ Wo^T ; also returns ckv
// Round 2: identical resubmit of the fp32 baseline (R1 failed on infra).
// ---------------------------------------------------------------------------

#define BDIM   2
#define SDIM   2048
#define DDIM   2048
#define HDIM   16
#define DHDIM  128
#define BS_ROWS 4096            // B*S

// scratch (allocation-free rule: __device__ globals)
__device__ float g_cq [BS_ROWS * DDIM];      // 32 MB
__device__ float g_ckv[BS_ROWS * DDIM];      // 32 MB
__device__ float g_Q  [BS_ROWS * DDIM];      // 32 MB
__device__ float g_KV [BS_ROWS * 2 * DDIM];  // 64 MB (K | V)
__device__ float g_O  [BS_ROWS * DDIM];      // 32 MB

// ---------------------------------------------------------------------------
// SGEMM: C[M,N] = A[M,K] @ B  (TB=false: B is [K,N];  TB=true: B is [N,K], use B^T)
// 128x128x8 tiles, 256 threads, 8x8 per-thread microtile.
// ---------------------------------------------------------------------------
template <bool TB>
__global__ __launch_bounds__(256, 2) void sgemm_kernel(
    const float* __restrict__ A, const float* __restrict__ B,
    float* __restrict__ C, int M, int N, int K)
{
    __shared__ float As[8][128];
    __shared__ float Bs[8][128];

    const int tid = threadIdx.x;
    const int m0  = blockIdx.y * 128;
    const int n0  = blockIdx.x * 128;
    const int ty  = tid >> 4, tx = tid & 15;

    float acc[8][8];
#pragma unroll
    for (int i = 0; i < 8; i++)
#pragma unroll
        for (int j = 0; j < 8; j++) acc[i][j] = 0.f;

    const int ar = tid >> 1;
    const int ac = (tid & 1) * 4;
    const float* Aptr = A + (size_t)(m0 + ar) * K + ac;

    for (int kt = 0; kt < K; kt += 8) {
        // A tile 128x8, stored transposed As[k][m]
        float4 av = *(const float4*)(Aptr + kt);
        As[ac + 0][ar] = av.x; As[ac + 1][ar] = av.y;
        As[ac + 2][ar] = av.z; As[ac + 3][ar] = av.w;

        if (!TB) {
            const int br = tid >> 5;            // 0..7 (k)
            const int bc = (tid & 31) * 4;      // 0..124 (n)
            float4 bv = *(const float4*)(B + (size_t)(kt + br) * N + n0 + bc);
            *(float4*)&Bs[br][bc] = bv;
        } else {
            const int bn = tid >> 1;            // 0..127 (n)
            const int bc = (tid & 1) * 4;       // 0 or 4 (k)
            float4 bv = *(const float4*)(B + (size_t)(n0 + bn) * K + kt + bc);
            Bs[bc + 0][bn] = bv.x; Bs[bc + 1][bn] = bv.y;
            Bs[bc + 2][bn] = bv.z; Bs[bc + 3][bn] = bv.w;
        }
        __syncthreads();

#pragma unroll
        for (int k = 0; k < 8; k++) {
            float4 a0 = *(const float4*)&As[k][ty * 8];
            float4 a1 = *(const float4*)&As[k][ty * 8 + 4];
            float4 b0 = *(const float4*)&Bs[k][tx * 8];
            float4 b1 = *(const float4*)&Bs[k][tx * 8 + 4];
            float a[8] = {a0.x, a0.y, a0.z, a0.w, a1.x, a1.y, a1.z, a1.w};
            float b[8] = {b0.x, b0.y, b0.z, b0.w, b1.x, b1.y, b1.z, b1.w};
#pragma unroll
            for (int i = 0; i < 8; i++)
#pragma unroll
                for (int j = 0; j < 8; j++)
                    acc[i][j] = fmaf(a[i], b[j], acc[i][j]);
        }
        __syncthreads();
    }

#pragma unroll
    for (int i = 0; i < 8; i++) {
        float* cp = C + (size_t)(m0 + ty * 8 + i) * N + n0 + tx * 8;
        float4 c0 = {acc[i][0], acc[i][1], acc[i][2], acc[i][3]};
        float4 c1 = {acc[i][4], acc[i][5], acc[i][6], acc[i][7]};
        *(float4*)cp       = c0;
        *(float4*)(cp + 4) = c1;
    }
}

// ---------------------------------------------------------------------------
// LayerNorm in-place over rows of D=2048; optionally mirrors result to out2.
// ---------------------------------------------------------------------------
__global__ void ln_kernel(float* __restrict__ X, const float* __restrict__ gamma,
                          const float* __restrict__ beta, float* __restrict__ out2)
{
    const int row = blockIdx.x;
    const int tid = threadIdx.x;
    float* xr = X + (size_t)row * DDIM;

    float v[8];
    float s = 0.f, sq = 0.f;
#pragma unroll
    for (int j = 0; j < 8; j++) {
        v[j] = xr[tid + j * 256];
        s  += v[j];
        sq += v[j] * v[j];
    }

    __shared__ float red[64];
#pragma unroll
    for (int off = 16; off; off >>= 1) {
        s  += __shfl_xor_sync(0xffffffffu, s,  off);
        sq += __shfl_xor_sync(0xffffffffu, sq, off);
    }
    const int wid = tid >> 5, lane = tid & 31;
    if (lane == 0) { red[wid] = s; red[32 + wid] = sq; }
    __syncthreads();
    if (wid == 0) {
        s  = (lane < 8) ? red[lane]      : 0.f;
        sq = (lane < 8) ? red[32 + lane] : 0.f;
#pragma unroll
        for (int off = 4; off; off >>= 1) {
            s  += __shfl_xor_sync(0xffffffffu, s,  off);
            sq += __shfl_xor_sync(0xffffffffu, sq, off);
        }
        if (lane == 0) { red[0] = s; red[1] = sq; }
    }
    __syncthreads();

    const float mean = red[0] * (1.f / DDIM);
    const float var  = red[1] * (1.f / DDIM) - mean * mean;
    const float rstd = rsqrtf(var + 1e-5f);

#pragma unroll
    for (int j = 0; j < 8; j++) {
        const int c = tid + j * 256;
        float y = (v[j] - mean) * rstd * gamma[c] + beta[c];
        xr[c] = y;
        if (out2) out2[(size_t)row * DDIM + c] = y;
    }
}

// ---------------------------------------------------------------------------
// RoPE applied in place to Q [BS,D] and the K half of KV [BS,2D].
// freq computed in double then rounded to fp32 to track the reference's fp32
// pow; the t*freq product is a single fp32 multiply, matching jnp.outer.
// ---------------------------------------------------------------------------
__global__ void rope_kernel(float* __restrict__ Q, float* __restrict__ KV)
{
    const int row = blockIdx.x;           // 0..4095
    const int t   = row & (SDIM - 1);     // position within sequence
    const int tid = threadIdx.x;          // 0..1023
    const int h   = tid >> 6;
    const int i   = tid & 63;

    const float freq = (float)exp(-(double)i * (log(10000.0) / 64.0));
    const float ang  = (float)t * freq;
    float sn, cs;
    sincosf(ang, &sn, &cs);

    const size_t qb = (size_t)row * DDIM + h * DHDIM + i;
    float x1 = Q[qb], x2 = Q[qb + 64];
    Q[qb]      = x1 * cs - x2 * sn;
    Q[qb + 64] = x2 * cs + x1 * sn;

    const size_t kb = (size_t)row * (2 * DDIM) + h * DHDIM + i;
    float y1 = KV[kb], y2 = KV[kb + 64];
    KV[kb]      = y1 * cs - y2 * sn;
    KV[kb + 64] = y2 * cs + y1 * sn;
}

// ---------------------------------------------------------------------------
// Flash attention (fp32, online softmax). BQ=BKV=64, dh=128.
// Q,K staged transposed in smem ([dim][row]) so the score phase reads
// conflict-free float4s; V staged [row][dim] for the PV phase.
// ---------------------------------------------------------------------------
#define ATTN_SMEM_FLOATS (128 * 68 * 2 + 64 * 132 + 64 * 66)
#define ATTN_SMEM_BYTES  (ATTN_SMEM_FLOATS * 4)

__global__ __launch_bounds__(256, 1) void attn_kernel(
    const float* __restrict__ Q, const float* __restrict__ KV, float* __restrict__ O)
{
    extern __shared__ float smx[];
    float* Qt = smx;                  // [128][68]  (dim-major)
    float* Kt = smx + 128 * 68;       // [128][68]
    float* Vs = Kt  + 128 * 68;       // [64][132]  (row-major)
    float* Ps = Vs  + 64 * 132;       // [64][66]

    const int qt = blockIdx.x, h = blockIdx.y, b = blockIdx.z;
    const int tid = threadIdx.x;
    const int ty = tid >> 4, tx = tid & 15;
    const float scale = 0.088388347648318447f;   // 1/sqrt(128)

    // stage Q tile transposed
    {
        const int r  = tid >> 2;
        const int c0 = tid & 3;
        const float* gq = Q + (size_t)(b * SDIM + qt * 64 + r) * DDIM + h * DHDIM;
#pragma unroll
        for (int rep = 0; rep < 8; rep++) {
            const int c4 = c0 + rep * 4;
            float4 v = *(const float4*)(gq + c4 * 4);
            Qt[(c4 * 4 + 0) * 68 + r] = v.x;
            Qt[(c4 * 4 + 1) * 68 + r] = v.y;
            Qt[(c4 * 4 + 2) * 68 + r] = v.z;
            Qt[(c4 * 4 + 3) * 68 + r] = v.w;
        }
    }

    float m_i[4], l_i[4], acc[4][8];
#pragma unroll
    for (int i = 0; i < 4; i++) {
        m_i[i] = -1e30f; l_i[i] = 0.f;
#pragma unroll
        for (int j = 0; j < 8; j++) acc[i][j] = 0.f;
    }

    for (int kt = 0; kt <= qt; kt++) {
        __syncthreads();   // previous iteration consumers done with Kt/Vs/Ps
        {
            const int r  = tid >> 2;
            const int c0 = tid & 3;
            const float* gk = KV + (size_t)(b * SDIM + kt * 64 + r) * (2 * DDIM) + h * DHDIM;
            const float* gv = gk + DDIM;
#pragma unroll
            for (int rep = 0; rep < 8; rep++) {
                const int c4 = c0 + rep * 4;
                float4 v = *(const float4*)(gk + c4 * 4);
                Kt[(c4 * 4 + 0) * 68 + r] = v.x;
                Kt[(c4 * 4 + 1) * 68 + r] = v.y;
                Kt[(c4 * 4 + 2) * 68 + r] = v.z;
                Kt[(c4 * 4 + 3) * 68 + r] = v.w;
                float4 w = *(const float4*)(gv + c4 * 4);
                *(float4*)&Vs[r * 132 + c4 * 4] = w;
            }
        }
        __syncthreads();

        // scores: 4x4 per thread over k=0..127
        float s[4][4];
#pragma unroll
        for (int i = 0; i < 4; i++)
#pragma unroll
            for (int j = 0; j < 4; j++) s[i][j] = 0.f;

#pragma unroll 8
        for (int k = 0; k < 128; k++) {
            float4 a  = *(const float4*)&Qt[k * 68 + ty * 4];
            float4 bb = *(const float4*)&Kt[k * 68 + tx * 4];
            float av[4] = {a.x, a.y, a.z, a.w};
            float bv[4] = {bb.x, bb.y, bb.z, bb.w};
#pragma unroll
            for (int i = 0; i < 4; i++)
#pragma unroll
                for (int j = 0; j < 4; j++)
                    s[i][j] = fmaf(av[i], bv[j], s[i][j]);
        }

        // scale + causal mask (only the diagonal tile needs masking)
        if (kt == qt) {
#pragma unroll
            for (int i = 0; i < 4; i++)
#pragma unroll
                for (int j = 0; j < 4; j++)
                    s[i][j] = (tx * 4 + j <= ty * 4 + i) ? s[i][j] * scale : -1e30f;
        } else {
#pragma unroll
            for (int i = 0; i < 4; i++)
#pragma unroll
                for (int j = 0; j < 4; j++) s[i][j] *= scale;
        }

        // online softmax update; row groups are 16 consecutive lanes
#pragma unroll
        for (int i = 0; i < 4; i++) {
            float r = fmaxf(fmaxf(s[i][0], s[i][1]), fmaxf(s[i][2], s[i][3]));
#pragma unroll
            for (int off = 8; off; off >>= 1)
                r = fmaxf(r, __shfl_xor_sync(0xffffffffu, r, off));
            const float mnew = fmaxf(m_i[i], r);
            const float corr = expf(m_i[i] - mnew);
            float ss = 0.f;
#pragma unroll
            for (int j = 0; j < 4; j++) {
                float p = expf(s[i][j] - mnew);
                s[i][j] = p;
                ss += p;
            }
#pragma unroll
            for (int off = 8; off; off >>= 1)
                ss += __shfl_xor_sync(0xffffffffu, ss, off);
            l_i[i] = l_i[i] * corr + ss;
            m_i[i] = mnew;
#pragma unroll
            for (int j = 0; j < 8; j++) acc[i][j] *= corr;
#pragma unroll
            for (int j = 0; j < 4; j++)
                Ps[(ty * 4 + i) * 66 + tx * 4 + j] = s[i][j];
        }
        __syncthreads();

        // O += P @ V  (rows ty*4.., dims tx*8..)
#pragma unroll 4
        for (int kk = 0; kk < 64; kk++) {
            float4 v0 = *(const float4*)&Vs[kk * 132 + tx * 8];
            float4 v1 = *(const float4*)&Vs[kk * 132 + tx * 8 + 4];
            float vv[8] = {v0.x, v0.y, v0.z, v0.w, v1.x, v1.y, v1.z, v1.w};
#pragma unroll
            for (int i = 0; i < 4; i++) {
                const float p = Ps[(ty * 4 + i) * 66 + kk];
#pragma unroll
                for (int j = 0; j < 8; j++)
                    acc[i][j] = fmaf(p, vv[j], acc[i][j]);
            }
        }
    }

    // epilogue: normalize and write O in [B,S,H*dh] layout
#pragma unroll
    for (int i = 0; i < 4; i++) {
        const float inv = 1.f / l_i[i];
        float* go = O + (size_t)(b * SDIM + qt * 64 + ty * 4 + i) * DDIM + h * DHDIM + tx * 8;
        float4 o0 = {acc[i][0] * inv, acc[i][1] * inv, acc[i][2] * inv, acc[i][3] * inv};
        float4 o1 = {acc[i][4] * inv, acc[i][5] * inv, acc[i][6] * inv, acc[i][7] * inv};
        *(float4*)go       = o0;
        *(float4*)(go + 4) = o1;
    }
}

// ---------------------------------------------------------------------------
extern "C" void kernel_launch(void* const* d_in, const int* in_sizes, int n_in,
                              void* d_out, int out_size)
{
    const float* x    = (const float*)d_in[0];
    const float* Wdq  = (const float*)d_in[1];
    const float* Wuq  = (const float*)d_in[2];
    const float* qg   = (const float*)d_in[3];
    const float* qb   = (const float*)d_in[4];
    const float* Wdkv = (const float*)d_in[5];
    const float* Wukv = (const float*)d_in[6];
    const float* kvg  = (const float*)d_in[7];
    const float* kvb  = (const float*)d_in[8];
    const float* Wo   = (const float*)d_in[9];
    float* out = (float*)d_out;

    float *cq, *ckv, *Qb, *KVb, *Ob;
    cudaGetSymbolAddress((void**)&cq,  g_cq);
    cudaGetSymbolAddress((void**)&ckv, g_ckv);
    cudaGetSymbolAddress((void**)&Qb,  g_Q);
    cudaGetSymbolAddress((void**)&KVb, g_KV);
    cudaGetSymbolAddress((void**)&Ob,  g_O);

    cudaFuncSetAttribute(attn_kernel, cudaFuncAttributeMaxDynamicSharedMemorySize,
                         ATTN_SMEM_BYTES);

    dim3 blk(256);

    // down-projections
    sgemm_kernel<false><<<dim3(16, 32), blk>>>(x, Wdq,  cq,  BS_ROWS, DDIM, DDIM);
    sgemm_kernel<false><<<dim3(16, 32), blk>>>(x, Wdkv, ckv, BS_ROWS, DDIM, DDIM);

    // layernorms (ckv LN also mirrors into the second output region)
    ln_kernel<<<BS_ROWS, 256>>>(cq, qg, qb, nullptr);
    float* ckv_out = (out_size >= 2 * BS_ROWS * DDIM)
                         ? (out + (size_t)BS_ROWS * DDIM) : nullptr;
    ln_kernel<<<BS_ROWS, 256>>>(ckv, kvg, kvb, ckv_out);

    // up-projections
    sgemm_kernel<false><<<dim3(16, 32), blk>>>(cq,  Wuq,  Qb,  BS_ROWS, DDIM,     DDIM);
    sgemm_kernel<false><<<dim3(32, 32), blk>>>(ckv, Wukv, KVb, BS_ROWS, 2 * DDIM, DDIM);

    // RoPE on Q and K
    rope_kernel<<<BS_ROWS, 1024>>>(Qb, KVb);

    // causal flash attention -> O in [B,S,D] layout
    attn_kernel<<<dim3(32, HDIM, BDIM), blk, ATTN_SMEM_BYTES>>>(Qb, KVb, Ob);

    // out = O @ Wo^T
    sgemm_kernel<true><<<dim3(16, 32), blk>>>(Ob, Wo, out, BS_ROWS, DDIM, DDIM);
}

// round 5
// speedup vs baseline: 1.6647x; 1.6647x over previous
#include <cuda_runtime.h>
#include <math.h>
#include <stdint.h>

// ---------------------------------------------------------------------------
// MLA prefill: B=2, S=2048, D=2048, H=16, dh=128
// Round 5: identical resubmit of R4 (infra failure, bench never ran).
// tf32 mma.sync tensor-core GEMMs; attention/LN/RoPE stay fp32.
// ---------------------------------------------------------------------------

#define BDIM   2
#define SDIM   2048
#define DDIM   2048
#define HDIM   16
#define DHDIM  128
#define BS_ROWS 4096            // B*S

// scratch (allocation-free rule: __device__ globals)
__device__ float g_cq [BS_ROWS * DDIM];
__device__ float g_ckv[BS_ROWS * DDIM];
__device__ float g_Q  [BS_ROWS * DDIM];
__device__ float g_KV [BS_ROWS * 2 * DDIM];
__device__ float g_O  [BS_ROWS * DDIM];
__device__ float g_Wt1[DDIM * DDIM];         // Wdq^T
__device__ float g_Wt2[DDIM * DDIM];         // Wdkv^T
__device__ float g_Wt3[DDIM * DDIM];         // Wuq^T
__device__ float g_Wt4[2 * DDIM * DDIM];     // Wukv^T

__device__ __forceinline__ float tf32_rna(float x) {
    uint32_t u;
    asm("cvt.rna.tf32.f32 %0, %1;" : "=r"(u) : "f"(x));
    return __uint_as_float(u);
}

__device__ __forceinline__ void mma_tf32_16x8x8(float* d, const uint32_t* a,
                                                const uint32_t* b) {
    asm volatile(
        "mma.sync.aligned.m16n8k8.row.col.f32.tf32.tf32.f32 "
        "{%0,%1,%2,%3}, {%4,%5,%6,%7}, {%8,%9}, {%0,%1,%2,%3};\n"
        : "+f"(d[0]), "+f"(d[1]), "+f"(d[2]), "+f"(d[3])
        : "r"(a[0]), "r"(a[1]), "r"(a[2]), "r"(a[3]), "r"(b[0]), "r"(b[1]));
}

// ---------------------------------------------------------------------------
// tf32 tensor-core GEMM: C[M,N] = A[M,K] @ Bt[N,K]^T (both K-major).
// CTA tile 128x128, K chunk 32, 256 threads = 8 warps (2 M x 4 N), each warp
// computes 64x32 via m16n8k8. Smem [128][36] pad -> conflict-free frag loads.
// Double-buffered with register prefetch.
// ---------------------------------------------------------------------------
#define TGP 36                           // smem row pitch (floats)
#define TG_TILE (128 * TGP)              // floats per tile buffer
#define TG_SMEM (4 * TG_TILE * 4)        // bytes: A0,A1,B0,B1

__global__ __launch_bounds__(256, 1) void tgemm_mma(
    const float* __restrict__ A, const float* __restrict__ Bt,
    float* __restrict__ C, int M, int N, int K)
{
    extern __shared__ float sm[];
    float* Abuf[2] = {sm, sm + TG_TILE};
    float* Bbuf[2] = {sm + 2 * TG_TILE, sm + 3 * TG_TILE};

    const int tid = threadIdx.x;
    const int wid = tid >> 5, lane = tid & 31;
    const int m0 = blockIdx.y * 128;
    const int n0 = blockIdx.x * 128;

    const int warp_m = wid & 1;          // 0..1  (64 rows)
    const int warp_n = wid >> 1;         // 0..3  (32 cols)
    const int g  = lane >> 2;            // 0..7
    const int t4 = lane & 3;             // 0..3

    // global loader mapping: 4 float4 per thread per operand per chunk
    const int lr = tid >> 3;             // 0..31
    const int lc = tid & 7;              // 0..7 (float4 within 32-col chunk)

    float acc[4][4][4];
#pragma unroll
    for (int mi = 0; mi < 4; mi++)
#pragma unroll
        for (int ni = 0; ni < 4; ni++)
#pragma unroll
            for (int q = 0; q < 4; q++) acc[mi][ni][q] = 0.f;

    const int nch = K >> 5;
    float4 pa[4], pb[4];

    // preload chunk 0
#pragma unroll
    for (int f = 0; f < 4; f++) {
        pa[f] = *(const float4*)(A  + (size_t)(m0 + lr + f * 32) * K + lc * 4);
        pb[f] = *(const float4*)(Bt + (size_t)(n0 + lr + f * 32) * K + lc * 4);
    }
#pragma unroll
    for (int f = 0; f < 4; f++) {
        float4 av = pa[f], bv = pb[f];
        av.x = tf32_rna(av.x); av.y = tf32_rna(av.y);
        av.z = tf32_rna(av.z); av.w = tf32_rna(av.w);
        bv.x = tf32_rna(bv.x); bv.y = tf32_rna(bv.y);
        bv.z = tf32_rna(bv.z); bv.w = tf32_rna(bv.w);
        *(float4*)&Abuf[0][(lr + f * 32) * TGP + lc * 4] = av;
        *(float4*)&Bbuf[0][(lr + f * 32) * TGP + lc * 4] = bv;
    }
    __syncthreads();

    for (int ch = 0; ch < nch; ch++) {
        const int cur = ch & 1, nxt = cur ^ 1;

        // issue next-chunk global loads (latency hidden under mma)
        if (ch + 1 < nch) {
            const int k0g = (ch + 1) * 32;
#pragma unroll
            for (int f = 0; f < 4; f++) {
                pa[f] = *(const float4*)(A  + (size_t)(m0 + lr + f * 32) * K + k0g + lc * 4);
                pb[f] = *(const float4*)(Bt + (size_t)(n0 + lr + f * 32) * K + k0g + lc * 4);
            }
        }

        const float* As = Abuf[cur];
        const float* Bs = Bbuf[cur];
#pragma unroll
        for (int ks = 0; ks < 4; ks++) {
            const int k0 = ks * 8;
            uint32_t afr[4][4], bfr[4][2];
#pragma unroll
            for (int mi = 0; mi < 4; mi++) {
                const int r16 = warp_m * 64 + mi * 16;
                afr[mi][0] = __float_as_uint(As[(r16 + g)     * TGP + k0 + t4]);
                afr[mi][1] = __float_as_uint(As[(r16 + g + 8) * TGP + k0 + t4]);
                afr[mi][2] = __float_as_uint(As[(r16 + g)     * TGP + k0 + t4 + 4]);
                afr[mi][3] = __float_as_uint(As[(r16 + g + 8) * TGP + k0 + t4 + 4]);
            }
#pragma unroll
            for (int ni = 0; ni < 4; ni++) {
                const int c8 = warp_n * 32 + ni * 8;
                bfr[ni][0] = __float_as_uint(Bs[(c8 + g) * TGP + k0 + t4]);
                bfr[ni][1] = __float_as_uint(Bs[(c8 + g) * TGP + k0 + t4 + 4]);
            }
#pragma unroll
            for (int mi = 0; mi < 4; mi++)
#pragma unroll
                for (int ni = 0; ni < 4; ni++)
                    mma_tf32_16x8x8(acc[mi][ni], afr[mi], bfr[ni]);
        }

        // stage next chunk into the other buffer
        if (ch + 1 < nch) {
#pragma unroll
            for (int f = 0; f < 4; f++) {
                float4 av = pa[f], bv = pb[f];
                av.x = tf32_rna(av.x); av.y = tf32_rna(av.y);
                av.z = tf32_rna(av.z); av.w = tf32_rna(av.w);
                bv.x = tf32_rna(bv.x); bv.y = tf32_rna(bv.y);
                bv.z = tf32_rna(bv.z); bv.w = tf32_rna(bv.w);
                *(float4*)&Abuf[nxt][(lr + f * 32) * TGP + lc * 4] = av;
                *(float4*)&Bbuf[nxt][(lr + f * 32) * TGP + lc * 4] = bv;
            }
        }
        __syncthreads();
    }

    // epilogue: C fragment layout -> global
#pragma unroll
    for (int mi = 0; mi < 4; mi++) {
        const int r16 = m0 + warp_m * 64 + mi * 16;
#pragma unroll
        for (int ni = 0; ni < 4; ni++) {
            const int cc = n0 + warp_n * 32 + ni * 8 + t4 * 2;
            float2 lo = {acc[mi][ni][0], acc[mi][ni][1]};
            float2 hi = {acc[mi][ni][2], acc[mi][ni][3]};
            *(float2*)(C + (size_t)(r16 + g)     * N + cc) = lo;
            *(float2*)(C + (size_t)(r16 + g + 8) * N + cc) = hi;
        }
    }
}

// ---------------------------------------------------------------------------
// 32x32 tiled transpose: Wt[C,R] = W[R,C]^T
// ---------------------------------------------------------------------------
__global__ void transpose_kernel(const float* __restrict__ W, float* __restrict__ Wt,
                                 int R, int C)
{
    __shared__ float t[32][33];
    const int c0 = blockIdx.x * 32, r0 = blockIdx.y * 32;
    const int x = threadIdx.x, y = threadIdx.y;
#pragma unroll
    for (int j = 0; j < 32; j += 8)
        t[y + j][x] = W[(size_t)(r0 + y + j) * C + c0 + x];
    __syncthreads();
#pragma unroll
    for (int j = 0; j < 32; j += 8)
        Wt[(size_t)(c0 + y + j) * R + r0 + x] = t[x][y + j];
}

// ---------------------------------------------------------------------------
// LayerNorm in-place over rows of D=2048; optionally mirrors result to out2.
// ---------------------------------------------------------------------------
__global__ void ln_kernel(float* __restrict__ X, const float* __restrict__ gamma,
                          const float* __restrict__ beta, float* __restrict__ out2)
{
    const int row = blockIdx.x;
    const int tid = threadIdx.x;
    float* xr = X + (size_t)row * DDIM;

    float v[8];
    float s = 0.f, sq = 0.f;
#pragma unroll
    for (int j = 0; j < 8; j++) {
        v[j] = xr[tid + j * 256];
        s  += v[j];
        sq += v[j] * v[j];
    }

    __shared__ float red[64];
#pragma unroll
    for (int off = 16; off; off >>= 1) {
        s  += __shfl_xor_sync(0xffffffffu, s,  off);
        sq += __shfl_xor_sync(0xffffffffu, sq, off);
    }
    const int wid = tid >> 5, lane = tid & 31;
    if (lane == 0) { red[wid] = s; red[32 + wid] = sq; }
    __syncthreads();
    if (wid == 0) {
        s  = (lane < 8) ? red[lane]      : 0.f;
        sq = (lane < 8) ? red[32 + lane] : 0.f;
#pragma unroll
        for (int off = 4; off; off >>= 1) {
            s  += __shfl_xor_sync(0xffffffffu, s,  off);
            sq += __shfl_xor_sync(0xffffffffu, sq, off);
        }
        if (lane == 0) { red[0] = s; red[1] = sq; }
    }
    __syncthreads();

    const float mean = red[0] * (1.f / DDIM);
    const float var  = red[1] * (1.f / DDIM) - mean * mean;
    const float rstd = rsqrtf(var + 1e-5f);

#pragma unroll
    for (int j = 0; j < 8; j++) {
        const int c = tid + j * 256;
        float y = (v[j] - mean) * rstd * gamma[c] + beta[c];
        xr[c] = y;
        if (out2) out2[(size_t)row * DDIM + c] = y;
    }
}

// ---------------------------------------------------------------------------
// RoPE applied in place to Q [BS,D] and the K half of KV [BS,2D].
// ---------------------------------------------------------------------------
__global__ void rope_kernel(float* __restrict__ Q, float* __restrict__ KV)
{
    const int row = blockIdx.x;
    const int t   = row & (SDIM - 1);
    const int tid = threadIdx.x;
    const int h   = tid >> 6;
    const int i   = tid & 63;

    const float freq = (float)exp(-(double)i * (log(10000.0) / 64.0));
    const float ang  = (float)t * freq;
    float sn, cs;
    sincosf(ang, &sn, &cs);

    const size_t qb = (size_t)row * DDIM + h * DHDIM + i;
    float x1 = Q[qb], x2 = Q[qb + 64];
    Q[qb]      = x1 * cs - x2 * sn;
    Q[qb + 64] = x2 * cs + x1 * sn;

    const size_t kb = (size_t)row * (2 * DDIM) + h * DHDIM + i;
    float y1 = KV[kb], y2 = KV[kb + 64];
    KV[kb]      = y1 * cs - y2 * sn;
    KV[kb + 64] = y2 * cs + y1 * sn;
}

// ---------------------------------------------------------------------------
// Flash attention (fp32, online softmax). BQ=BKV=64, dh=128. (unchanged)
// ---------------------------------------------------------------------------
#define ATTN_SMEM_FLOATS (128 * 68 * 2 + 64 * 132 + 64 * 66)
#define ATTN_SMEM_BYTES  (ATTN_SMEM_FLOATS * 4)

__global__ __launch_bounds__(256, 1) void attn_kernel(
    const float* __restrict__ Q, const float* __restrict__ KV, float* __restrict__ O)
{
    extern __shared__ float smx[];
    float* Qt = smx;
    float* Kt = smx + 128 * 68;
    float* Vs = Kt  + 128 * 68;
    float* Ps = Vs  + 64 * 132;

    const int qt = blockIdx.x, h = blockIdx.y, b = blockIdx.z;
    const int tid = threadIdx.x;
    const int ty = tid >> 4, tx = tid & 15;
    const float scale = 0.088388347648318447f;

    {
        const int r  = tid >> 2;
        const int c0 = tid & 3;
        const float* gq = Q + (size_t)(b * SDIM + qt * 64 + r) * DDIM + h * DHDIM;
#pragma unroll
        for (int rep = 0; rep < 8; rep++) {
            const int c4 = c0 + rep * 4;
            float4 v = *(const float4*)(gq + c4 * 4);
            Qt[(c4 * 4 + 0) * 68 + r] = v.x;
            Qt[(c4 * 4 + 1) * 68 + r] = v.y;
            Qt[(c4 * 4 + 2) * 68 + r] = v.z;
            Qt[(c4 * 4 + 3) * 68 + r] = v.w;
        }
    }

    float m_i[4], l_i[4], acc[4][8];
#pragma unroll
    for (int i = 0; i < 4; i++) {
        m_i[i] = -1e30f; l_i[i] = 0.f;
#pragma unroll
        for (int j = 0; j < 8; j++) acc[i][j] = 0.f;
    }

    for (int kt = 0; kt <= qt; kt++) {
        __syncthreads();
        {
            const int r  = tid >> 2;
            const int c0 = tid & 3;
            const float* gk = KV + (size_t)(b * SDIM + kt * 64 + r) * (2 * DDIM) + h * DHDIM;
            const float* gv = gk + DDIM;
#pragma unroll
            for (int rep = 0; rep < 8; rep++) {
                const int c4 = c0 + rep * 4;
                float4 v = *(const float4*)(gk + c4 * 4);
                Kt[(c4 * 4 + 0) * 68 + r] = v.x;
                Kt[(c4 * 4 + 1) * 68 + r] = v.y;
                Kt[(c4 * 4 + 2) * 68 + r] = v.z;
                Kt[(c4 * 4 + 3) * 68 + r] = v.w;
                float4 w = *(const float4*)(gv + c4 * 4);
                *(float4*)&Vs[r * 132 + c4 * 4] = w;
            }
        }
        __syncthreads();

        float s[4][4];
#pragma unroll
        for (int i = 0; i < 4; i++)
#pragma unroll
            for (int j = 0; j < 4; j++) s[i][j] = 0.f;

#pragma unroll 8
        for (int k = 0; k < 128; k++) {
            float4 a  = *(const float4*)&Qt[k * 68 + ty * 4];
            float4 bb = *(const float4*)&Kt[k * 68 + tx * 4];
            float av[4] = {a.x, a.y, a.z, a.w};
            float bv[4] = {bb.x, bb.y, bb.z, bb.w};
#pragma unroll
            for (int i = 0; i < 4; i++)
#pragma unroll
                for (int j = 0; j < 4; j++)
                    s[i][j] = fmaf(av[i], bv[j], s[i][j]);
        }

        if (kt == qt) {
#pragma unroll
            for (int i = 0; i < 4; i++)
#pragma unroll
                for (int j = 0; j < 4; j++)
                    s[i][j] = (tx * 4 + j <= ty * 4 + i) ? s[i][j] * scale : -1e30f;
        } else {
#pragma unroll
            for (int i = 0; i < 4; i++)
#pragma unroll
                for (int j = 0; j < 4; j++) s[i][j] *= scale;
        }

#pragma unroll
        for (int i = 0; i < 4; i++) {
            float r = fmaxf(fmaxf(s[i][0], s[i][1]), fmaxf(s[i][2], s[i][3]));
#pragma unroll
            for (int off = 8; off; off >>= 1)
                r = fmaxf(r, __shfl_xor_sync(0xffffffffu, r, off));
            const float mnew = fmaxf(m_i[i], r);
            const float corr = expf(m_i[i] - mnew);
            float ss = 0.f;
#pragma unroll
            for (int j = 0; j < 4; j++) {
                float p = expf(s[i][j] - mnew);
                s[i][j] = p;
                ss += p;
            }
#pragma unroll
            for (int off = 8; off; off >>= 1)
                ss += __shfl_xor_sync(0xffffffffu, ss, off);
            l_i[i] = l_i[i] * corr + ss;
            m_i[i] = mnew;
#pragma unroll
            for (int j = 0; j < 8; j++) acc[i][j] *= corr;
#pragma unroll
            for (int j = 0; j < 4; j++)
                Ps[(ty * 4 + i) * 66 + tx * 4 + j] = s[i][j];
        }
        __syncthreads();

#pragma unroll 4
        for (int kk = 0; kk < 64; kk++) {
            float4 v0 = *(const float4*)&Vs[kk * 132 + tx * 8];
            float4 v1 = *(const float4*)&Vs[kk * 132 + tx * 8 + 4];
            float vv[8] = {v0.x, v0.y, v0.z, v0.w, v1.x, v1.y, v1.z, v1.w};
#pragma unroll
            for (int i = 0; i < 4; i++) {
                const float p = Ps[(ty * 4 + i) * 66 + kk];
#pragma unroll
                for (int j = 0; j < 8; j++)
                    acc[i][j] = fmaf(p, vv[j], acc[i][j]);
            }
        }
    }

#pragma unroll
    for (int i = 0; i < 4; i++) {
        const float inv = 1.f / l_i[i];
        float* go = O + (size_t)(b * SDIM + qt * 64 + ty * 4 + i) * DDIM + h * DHDIM + tx * 8;
        float4 o0 = {acc[i][0] * inv, acc[i][1] * inv, acc[i][2] * inv, acc[i][3] * inv};
        float4 o1 = {acc[i][4] * inv, acc[i][5] * inv, acc[i][6] * inv, acc[i][7] * inv};
        *(float4*)go       = o0;
        *(float4*)(go + 4) = o1;
    }
}

// ---------------------------------------------------------------------------
extern "C" void kernel_launch(void* const* d_in, const int* in_sizes, int n_in,
                              void* d_out, int out_size)
{
    const float* x    = (const float*)d_in[0];
    const float* Wdq  = (const float*)d_in[1];
    const float* Wuq  = (const float*)d_in[2];
    const float* qg   = (const float*)d_in[3];
    const float* qb   = (const float*)d_in[4];
    const float* Wdkv = (const float*)d_in[5];
    const float* Wukv = (const float*)d_in[6];
    const float* kvg  = (const float*)d_in[7];
    const float* kvb  = (const float*)d_in[8];
    const float* Wo   = (const float*)d_in[9];
    float* out = (float*)d_out;

    float *cq, *ckv, *Qb, *KVb, *Ob, *Wt1, *Wt2, *Wt3, *Wt4;
    cudaGetSymbolAddress((void**)&cq,  g_cq);
    cudaGetSymbolAddress((void**)&ckv, g_ckv);
    cudaGetSymbolAddress((void**)&Qb,  g_Q);
    cudaGetSymbolAddress((void**)&KVb, g_KV);
    cudaGetSymbolAddress((void**)&Ob,  g_O);
    cudaGetSymbolAddress((void**)&Wt1, g_Wt1);
    cudaGetSymbolAddress((void**)&Wt2, g_Wt2);
    cudaGetSymbolAddress((void**)&Wt3, g_Wt3);
    cudaGetSymbolAddress((void**)&Wt4, g_Wt4);

    cudaFuncSetAttribute(attn_kernel, cudaFuncAttributeMaxDynamicSharedMemorySize,
                         ATTN_SMEM_BYTES);
    cudaFuncSetAttribute(tgemm_mma, cudaFuncAttributeMaxDynamicSharedMemorySize,
                         TG_SMEM);

    dim3 tb(32, 8);
    // weight transposes ([K,N] -> [N,K] so both GEMM operands are K-major)
    transpose_kernel<<<dim3(64,  64), tb>>>(Wdq,  Wt1, DDIM, DDIM);
    transpose_kernel<<<dim3(64,  64), tb>>>(Wdkv, Wt2, DDIM, DDIM);
    transpose_kernel<<<dim3(64,  64), tb>>>(Wuq,  Wt3, DDIM, DDIM);
    transpose_kernel<<<dim3(128, 64), tb>>>(Wukv, Wt4, DDIM, 2 * DDIM);

    dim3 blk(256);

    // down-projections (tf32 mma)
    tgemm_mma<<<dim3(16, 32), blk, TG_SMEM>>>(x, Wt1, cq,  BS_ROWS, DDIM, DDIM);
    tgemm_mma<<<dim3(16, 32), blk, TG_SMEM>>>(x, Wt2, ckv, BS_ROWS, DDIM, DDIM);

    // layernorms (ckv LN mirrors into second output region)
    ln_kernel<<<BS_ROWS, 256>>>(cq, qg, qb, nullptr);
    float* ckv_out = (out_size >= 2 * BS_ROWS * DDIM)
                         ? (out + (size_t)BS_ROWS * DDIM) : nullptr;
    ln_kernel<<<BS_ROWS, 256>>>(ckv, kvg, kvb, ckv_out);

    // up-projections (tf32 mma)
    tgemm_mma<<<dim3(16, 32), blk, TG_SMEM>>>(cq,  Wt3, Qb,  BS_ROWS, DDIM,     DDIM);
    tgemm_mma<<<dim3(32, 32), blk, TG_SMEM>>>(ckv, Wt4, KVb, BS_ROWS, 2 * DDIM, DDIM);

    // RoPE on Q and K
    rope_kernel<<<BS_ROWS, 1024>>>(Qb, KVb);

    // causal flash attention -> O in [B,S,D] layout (fp32)
    attn_kernel<<<dim3(32, HDIM, BDIM), blk, ATTN_SMEM_BYTES>>>(Qb, KVb, Ob);

    // out = O @ Wo^T  (Wo is already [N,K] for this contraction)
    tgemm_mma<<<dim3(16, 32), blk, TG_SMEM>>>(Ob, Wo, out, BS_ROWS, DDIM, DDIM);
}

// round 6
// speedup vs baseline: 1.8327x; 1.1010x over previous
#include <cuda_runtime.h>
#include <math.h>
#include <stdint.h>

// ---------------------------------------------------------------------------
// MLA prefill: B=2, S=2048, D=2048, H=16, dh=128
// Round 6: attention moved to tensor cores via split-tf32 (3-pass Markidis)
// mma.sync for QK^T and PV -> fp32-accurate, tensor-pipe-bound attention.
// GEMMs unchanged from R5 (tf32 mma.sync).
// ---------------------------------------------------------------------------

#define BDIM   2
#define SDIM   2048
#define DDIM   2048
#define HDIM   16
#define DHDIM  128
#define BS_ROWS 4096            // B*S

__device__ float g_cq [BS_ROWS * DDIM];
__device__ float g_ckv[BS_ROWS * DDIM];
__device__ float g_Q  [BS_ROWS * DDIM];
__device__ float g_KV [BS_ROWS * 2 * DDIM];
__device__ float g_O  [BS_ROWS * DDIM];
__device__ float g_Wt1[DDIM * DDIM];
__device__ float g_Wt2[DDIM * DDIM];
__device__ float g_Wt3[DDIM * DDIM];
__device__ float g_Wt4[2 * DDIM * DDIM];

__device__ __forceinline__ float tf32_rna(float x) {
    uint32_t u;
    asm("cvt.rna.tf32.f32 %0, %1;" : "=r"(u) : "f"(x));
    return __uint_as_float(u);
}

__device__ __forceinline__ void mma_tf32_16x8x8(float* d, const uint32_t* a,
                                                const uint32_t* b) {
    asm volatile(
        "mma.sync.aligned.m16n8k8.row.col.f32.tf32.tf32.f32 "
        "{%0,%1,%2,%3}, {%4,%5,%6,%7}, {%8,%9}, {%0,%1,%2,%3};\n"
        : "+f"(d[0]), "+f"(d[1]), "+f"(d[2]), "+f"(d[3])
        : "r"(a[0]), "r"(a[1]), "r"(a[2]), "r"(a[3]), "r"(b[0]), "r"(b[1]));
}

// ---------------------------------------------------------------------------
// tf32 tensor-core GEMM (unchanged from R5): C[M,N] = A[M,K] @ Bt[N,K]^T
// ---------------------------------------------------------------------------
#define TGP 36
#define TG_TILE (128 * TGP)
#define TG_SMEM (4 * TG_TILE * 4)

__global__ __launch_bounds__(256, 1) void tgemm_mma(
    const float* __restrict__ A, const float* __restrict__ Bt,
    float* __restrict__ C, int M, int N, int K)
{
    extern __shared__ float sm[];
    float* Abuf[2] = {sm, sm + TG_TILE};
    float* Bbuf[2] = {sm + 2 * TG_TILE, sm + 3 * TG_TILE};

    const int tid = threadIdx.x;
    const int wid = tid >> 5, lane = tid & 31;
    const int m0 = blockIdx.y * 128;
    const int n0 = blockIdx.x * 128;

    const int warp_m = wid & 1;
    const int warp_n = wid >> 1;
    const int g  = lane >> 2;
    const int t4 = lane & 3;

    const int lr = tid >> 3;
    const int lc = tid & 7;

    float acc[4][4][4];
#pragma unroll
    for (int mi = 0; mi < 4; mi++)
#pragma unroll
        for (int ni = 0; ni < 4; ni++)
#pragma unroll
            for (int q = 0; q < 4; q++) acc[mi][ni][q] = 0.f;

    const int nch = K >> 5;
    float4 pa[4], pb[4];

#pragma unroll
    for (int f = 0; f < 4; f++) {
        pa[f] = *(const float4*)(A  + (size_t)(m0 + lr + f * 32) * K + lc * 4);
        pb[f] = *(const float4*)(Bt + (size_t)(n0 + lr + f * 32) * K + lc * 4);
    }
#pragma unroll
    for (int f = 0; f < 4; f++) {
        float4 av = pa[f], bv = pb[f];
        av.x = tf32_rna(av.x); av.y = tf32_rna(av.y);
        av.z = tf32_rna(av.z); av.w = tf32_rna(av.w);
        bv.x = tf32_rna(bv.x); bv.y = tf32_rna(bv.y);
        bv.z = tf32_rna(bv.z); bv.w = tf32_rna(bv.w);
        *(float4*)&Abuf[0][(lr + f * 32) * TGP + lc * 4] = av;
        *(float4*)&Bbuf[0][(lr + f * 32) * TGP + lc * 4] = bv;
    }
    __syncthreads();

    for (int ch = 0; ch < nch; ch++) {
        const int cur = ch & 1, nxt = cur ^ 1;

        if (ch + 1 < nch) {
            const int k0g = (ch + 1) * 32;
#pragma unroll
            for (int f = 0; f < 4; f++) {
                pa[f] = *(const float4*)(A  + (size_t)(m0 + lr + f * 32) * K + k0g + lc * 4);
                pb[f] = *(const float4*)(Bt + (size_t)(n0 + lr + f * 32) * K + k0g + lc * 4);
            }
        }

        const float* As = Abuf[cur];
        const float* Bs = Bbuf[cur];
#pragma unroll
        for (int ks = 0; ks < 4; ks++) {
            const int k0 = ks * 8;
            uint32_t afr[4][4], bfr[4][2];
#pragma unroll
            for (int mi = 0; mi < 4; mi++) {
                const int r16 = warp_m * 64 + mi * 16;
                afr[mi][0] = __float_as_uint(As[(r16 + g)     * TGP + k0 + t4]);
                afr[mi][1] = __float_as_uint(As[(r16 + g + 8) * TGP + k0 + t4]);
                afr[mi][2] = __float_as_uint(As[(r16 + g)     * TGP + k0 + t4 + 4]);
                afr[mi][3] = __float_as_uint(As[(r16 + g + 8) * TGP + k0 + t4 + 4]);
            }
#pragma unroll
            for (int ni = 0; ni < 4; ni++) {
                const int c8 = warp_n * 32 + ni * 8;
                bfr[ni][0] = __float_as_uint(Bs[(c8 + g) * TGP + k0 + t4]);
                bfr[ni][1] = __float_as_uint(Bs[(c8 + g) * TGP + k0 + t4 + 4]);
            }
#pragma unroll
            for (int mi = 0; mi < 4; mi++)
#pragma unroll
                for (int ni = 0; ni < 4; ni++)
                    mma_tf32_16x8x8(acc[mi][ni], afr[mi], bfr[ni]);
        }

        if (ch + 1 < nch) {
#pragma unroll
            for (int f = 0; f < 4; f++) {
                float4 av = pa[f], bv = pb[f];
                av.x = tf32_rna(av.x); av.y = tf32_rna(av.y);
                av.z = tf32_rna(av.z); av.w = tf32_rna(av.w);
                bv.x = tf32_rna(bv.x); bv.y = tf32_rna(bv.y);
                bv.z = tf32_rna(bv.z); bv.w = tf32_rna(bv.w);
                *(float4*)&Abuf[nxt][(lr + f * 32) * TGP + lc * 4] = av;
                *(float4*)&Bbuf[nxt][(lr + f * 32) * TGP + lc * 4] = bv;
            }
        }
        __syncthreads();
    }

#pragma unroll
    for (int mi = 0; mi < 4; mi++) {
        const int r16 = m0 + warp_m * 64 + mi * 16;
#pragma unroll
        for (int ni = 0; ni < 4; ni++) {
            const int cc = n0 + warp_n * 32 + ni * 8 + t4 * 2;
            float2 lo = {acc[mi][ni][0], acc[mi][ni][1]};
            float2 hi = {acc[mi][ni][2], acc[mi][ni][3]};
            *(float2*)(C + (size_t)(r16 + g)     * N + cc) = lo;
            *(float2*)(C + (size_t)(r16 + g + 8) * N + cc) = hi;
        }
    }
}

// ---------------------------------------------------------------------------
__global__ void transpose_kernel(const float* __restrict__ W, float* __restrict__ Wt,
                                 int R, int C)
{
    __shared__ float t[32][33];
    const int c0 = blockIdx.x * 32, r0 = blockIdx.y * 32;
    const int x = threadIdx.x, y = threadIdx.y;
#pragma unroll
    for (int j = 0; j < 32; j += 8)
        t[y + j][x] = W[(size_t)(r0 + y + j) * C + c0 + x];
    __syncthreads();
#pragma unroll
    for (int j = 0; j < 32; j += 8)
        Wt[(size_t)(c0 + y + j) * R + r0 + x] = t[x][y + j];
}

// ---------------------------------------------------------------------------
__global__ void ln_kernel(float* __restrict__ X, const float* __restrict__ gamma,
                          const float* __restrict__ beta, float* __restrict__ out2)
{
    const int row = blockIdx.x;
    const int tid = threadIdx.x;
    float* xr = X + (size_t)row * DDIM;

    float v[8];
    float s = 0.f, sq = 0.f;
#pragma unroll
    for (int j = 0; j < 8; j++) {
        v[j] = xr[tid + j * 256];
        s  += v[j];
        sq += v[j] * v[j];
    }

    __shared__ float red[64];
#pragma unroll
    for (int off = 16; off; off >>= 1) {
        s  += __shfl_xor_sync(0xffffffffu, s,  off);
        sq += __shfl_xor_sync(0xffffffffu, sq, off);
    }
    const int wid = tid >> 5, lane = tid & 31;
    if (lane == 0) { red[wid] = s; red[32 + wid] = sq; }
    __syncthreads();
    if (wid == 0) {
        s  = (lane < 8) ? red[lane]      : 0.f;
        sq = (lane < 8) ? red[32 + lane] : 0.f;
#pragma unroll
        for (int off = 4; off; off >>= 1) {
            s  += __shfl_xor_sync(0xffffffffu, s,  off);
            sq += __shfl_xor_sync(0xffffffffu, sq, off);
        }
        if (lane == 0) { red[0] = s; red[1] = sq; }
    }
    __syncthreads();

    const float mean = red[0] * (1.f / DDIM);
    const float var  = red[1] * (1.f / DDIM) - mean * mean;
    const float rstd = rsqrtf(var + 1e-5f);

#pragma unroll
    for (int j = 0; j < 8; j++) {
        const int c = tid + j * 256;
        float y = (v[j] - mean) * rstd * gamma[c] + beta[c];
        xr[c] = y;
        if (out2) out2[(size_t)row * DDIM + c] = y;
    }
}

// ---------------------------------------------------------------------------
__global__ void rope_kernel(float* __restrict__ Q, float* __restrict__ KV)
{
    const int row = blockIdx.x;
    const int t   = row & (SDIM - 1);
    const int tid = threadIdx.x;
    const int h   = tid >> 6;
    const int i   = tid & 63;

    const float freq = (float)exp(-(double)i * (log(10000.0) / 64.0));
    const float ang  = (float)t * freq;
    float sn, cs;
    sincosf(ang, &sn, &cs);

    const size_t qb = (size_t)row * DDIM + h * DHDIM + i;
    float x1 = Q[qb], x2 = Q[qb + 64];
    Q[qb]      = x1 * cs - x2 * sn;
    Q[qb + 64] = x2 * cs + x1 * sn;

    const size_t kb = (size_t)row * (2 * DDIM) + h * DHDIM + i;
    float y1 = KV[kb], y2 = KV[kb + 64];
    KV[kb]      = y1 * cs - y2 * sn;
    KV[kb + 64] = y2 * cs + y1 * sn;
}

// ---------------------------------------------------------------------------
// Flash attention with split-tf32 tensor cores.
// CTA = one (b, h, 64-row q-tile). 256 threads = 8 warps.
// QK: warps 2D (4 m x 2 n), each 16x32 of S. PV: (4 m x 2 dh-half), each 16x64.
// Q/K pre-split hi/lo K-major [64][132]; V transposed [128][68] hi/lo;
// P via smem [64][68] with on-the-fly split. 3-pass mma => fp32-accurate.
// ---------------------------------------------------------------------------
#define AQP 132
#define AVP 68
#define OFF_QH 0
#define OFF_QL 8448
#define OFF_KH 16896
#define OFF_KL 25344
#define OFF_VH 33792
#define OFF_VL 42496
#define OFF_PS 51200
#define OFF_M  55552
#define OFF_L  55616
#define OFF_C  55680
#define ATTN_SMEM_FLOATS 55744
#define ATTN_SMEM_BYTES  (ATTN_SMEM_FLOATS * 4)

__global__ __launch_bounds__(256, 1) void attn_mma_kernel(
    const float* __restrict__ Q, const float* __restrict__ KV, float* __restrict__ O)
{
    extern __shared__ float smx[];
    float* Qh = smx + OFF_QH;
    float* Ql = smx + OFF_QL;
    float* Kh = smx + OFF_KH;
    float* Kl = smx + OFF_KL;
    float* Vh = smx + OFF_VH;
    float* Vl = smx + OFF_VL;
    float* Ps = smx + OFF_PS;
    float* Mr = smx + OFF_M;
    float* Lr = smx + OFF_L;
    float* Cr = smx + OFF_C;

    const int qt = blockIdx.x, h = blockIdx.y, b = blockIdx.z;
    const int tid = threadIdx.x;
    const int wid = tid >> 5, lane = tid & 31;
    const int g = lane >> 2, t4 = lane & 3;
    const float scale = 0.088388347648318447f;   // 1/sqrt(128)

    const int wm = wid & 3;          // 16-row group
    const int wn = wid >> 2;         // QK col half / PV dh half

    // ---- stage Q tile (hi/lo split, K-major [64][132]) + init m/l ----
    {
        const int r  = tid >> 2;
        const int c0 = tid & 3;
        const float* gq = Q + (size_t)(b * SDIM + qt * 64 + r) * DDIM + h * DHDIM;
#pragma unroll
        for (int rep = 0; rep < 8; rep++) {
            const int c4 = c0 + rep * 4;
            float4 v = *(const float4*)(gq + c4 * 4);
            float vv[4] = {v.x, v.y, v.z, v.w};
#pragma unroll
            for (int j = 0; j < 4; j++) {
                const int col = c4 * 4 + j;
                float hi = tf32_rna(vv[j]);
                Qh[r * AQP + col] = hi;
                Ql[r * AQP + col] = tf32_rna(vv[j] - hi);
            }
        }
        if (tid < 64) { Mr[tid] = -1e30f; Lr[tid] = 0.f; }
    }

    float acc_o[8][4];
#pragma unroll
    for (int ni = 0; ni < 8; ni++)
#pragma unroll
        for (int q = 0; q < 4; q++) acc_o[ni][q] = 0.f;

    for (int kt = 0; kt <= qt; kt++) {
        __syncthreads();   // prev PV done with Ps/Vh/Vl; QK done with Kh/Kl

        // ---- stage K (split, [key][132]) and V (split, transposed [dh][68]) ----
        {
            const int r  = tid >> 2;
            const int c0 = tid & 3;
            const float* gk = KV + (size_t)(b * SDIM + kt * 64 + r) * (2 * DDIM) + h * DHDIM;
            const float* gv = gk + DDIM;
#pragma unroll
            for (int rep = 0; rep < 8; rep++) {
                const int c4 = c0 + rep * 4;
                float4 kv4 = *(const float4*)(gk + c4 * 4);
                float4 vv4 = *(const float4*)(gv + c4 * 4);
                float kk[4] = {kv4.x, kv4.y, kv4.z, kv4.w};
                float vv[4] = {vv4.x, vv4.y, vv4.z, vv4.w};
#pragma unroll
                for (int j = 0; j < 4; j++) {
                    const int col = c4 * 4 + j;
                    float khi = tf32_rna(kk[j]);
                    Kh[r * AQP + col] = khi;
                    Kl[r * AQP + col] = tf32_rna(kk[j] - khi);
                    float vhi = tf32_rna(vv[j]);
                    Vh[col * AVP + r] = vhi;
                    Vl[col * AVP + r] = tf32_rna(vv[j] - vhi);
                }
            }
        }
        __syncthreads();

        // ---- QK^T: S[16x32] per warp, 3-pass split-tf32 ----
        float sacc[4][4];
#pragma unroll
        for (int ni = 0; ni < 4; ni++)
#pragma unroll
            for (int q = 0; q < 4; q++) sacc[ni][q] = 0.f;

#pragma unroll
        for (int ch = 0; ch < 16; ch++) {
            const int k0 = ch * 8;
            uint32_t ah[4], al[4];
            const int r0 = wm * 16;
            ah[0] = __float_as_uint(Qh[(r0 + g)     * AQP + k0 + t4]);
            ah[1] = __float_as_uint(Qh[(r0 + g + 8) * AQP + k0 + t4]);
            ah[2] = __float_as_uint(Qh[(r0 + g)     * AQP + k0 + t4 + 4]);
            ah[3] = __float_as_uint(Qh[(r0 + g + 8) * AQP + k0 + t4 + 4]);
            al[0] = __float_as_uint(Ql[(r0 + g)     * AQP + k0 + t4]);
            al[1] = __float_as_uint(Ql[(r0 + g + 8) * AQP + k0 + t4]);
            al[2] = __float_as_uint(Ql[(r0 + g)     * AQP + k0 + t4 + 4]);
            al[3] = __float_as_uint(Ql[(r0 + g + 8) * AQP + k0 + t4 + 4]);
#pragma unroll
            for (int ni = 0; ni < 4; ni++) {
                const int c8 = wn * 32 + ni * 8;
                uint32_t bh[2], bl[2];
                bh[0] = __float_as_uint(Kh[(c8 + g) * AQP + k0 + t4]);
                bh[1] = __float_as_uint(Kh[(c8 + g) * AQP + k0 + t4 + 4]);
                bl[0] = __float_as_uint(Kl[(c8 + g) * AQP + k0 + t4]);
                bl[1] = __float_as_uint(Kl[(c8 + g) * AQP + k0 + t4 + 4]);
                mma_tf32_16x8x8(sacc[ni], ah, bh);
                mma_tf32_16x8x8(sacc[ni], ah, bl);
                mma_tf32_16x8x8(sacc[ni], al, bh);
            }
        }

        // ---- scale + causal mask -> Ps ----
        const bool diag = (kt == qt);
#pragma unroll
        for (int ni = 0; ni < 4; ni++) {
            const int c0 = wn * 32 + ni * 8 + t4 * 2;
            const int rA = wm * 16 + g, rB = rA + 8;
            float s0 = sacc[ni][0] * scale, s1 = sacc[ni][1] * scale;
            float s2 = sacc[ni][2] * scale, s3 = sacc[ni][3] * scale;
            if (diag) {
                if (c0     > rA) s0 = -1e30f;
                if (c0 + 1 > rA) s1 = -1e30f;
                if (c0     > rB) s2 = -1e30f;
                if (c0 + 1 > rB) s3 = -1e30f;
            }
            Ps[rA * AVP + c0]     = s0;
            Ps[rA * AVP + c0 + 1] = s1;
            Ps[rB * AVP + c0]     = s2;
            Ps[rB * AVP + c0 + 1] = s3;
        }
        __syncthreads();

        // ---- online softmax (4 threads per row, quad shuffles) ----
        {
            const int row = tid >> 2;
            const int q4  = tid & 3;
            float* pr = Ps + row * AVP + q4 * 16;
            float lmax = -1e30f;
#pragma unroll
            for (int j = 0; j < 16; j++) lmax = fmaxf(lmax, pr[j]);
            lmax = fmaxf(lmax, __shfl_xor_sync(0xffffffffu, lmax, 1));
            lmax = fmaxf(lmax, __shfl_xor_sync(0xffffffffu, lmax, 2));
            const float mold = Mr[row];
            const float mnew = fmaxf(mold, lmax);
            float lsum = 0.f;
#pragma unroll
            for (int j = 0; j < 16; j++) {
                float p = expf(pr[j] - mnew);
                pr[j] = p;
                lsum += p;
            }
            lsum += __shfl_xor_sync(0xffffffffu, lsum, 1);
            lsum += __shfl_xor_sync(0xffffffffu, lsum, 2);
            if (q4 == 0) {
                const float corr = expf(mold - mnew);
                Cr[row] = corr;
                Lr[row] = Lr[row] * corr + lsum;
                Mr[row] = mnew;
            }
        }
        __syncthreads();

        // ---- PV: O[16x64] per warp, rescale then 3-pass split-tf32 ----
        {
            const float cg  = Cr[wm * 16 + g];
            const float cg8 = Cr[wm * 16 + g + 8];
#pragma unroll
            for (int ni = 0; ni < 8; ni++) {
                acc_o[ni][0] *= cg;  acc_o[ni][1] *= cg;
                acc_o[ni][2] *= cg8; acc_o[ni][3] *= cg8;
            }
#pragma unroll
            for (int ch = 0; ch < 8; ch++) {
                const int k0 = ch * 8;
                const int r0 = wm * 16;
                float p0 = Ps[(r0 + g)     * AVP + k0 + t4];
                float p1 = Ps[(r0 + g + 8) * AVP + k0 + t4];
                float p2 = Ps[(r0 + g)     * AVP + k0 + t4 + 4];
                float p3 = Ps[(r0 + g + 8) * AVP + k0 + t4 + 4];
                uint32_t ah[4], al[4];
                float h0 = tf32_rna(p0), h1 = tf32_rna(p1);
                float h2 = tf32_rna(p2), h3 = tf32_rna(p3);
                ah[0] = __float_as_uint(h0); ah[1] = __float_as_uint(h1);
                ah[2] = __float_as_uint(h2); ah[3] = __float_as_uint(h3);
                al[0] = __float_as_uint(tf32_rna(p0 - h0));
                al[1] = __float_as_uint(tf32_rna(p1 - h1));
                al[2] = __float_as_uint(tf32_rna(p2 - h2));
                al[3] = __float_as_uint(tf32_rna(p3 - h3));
#pragma unroll
                for (int ni = 0; ni < 8; ni++) {
                    const int c8 = wn * 64 + ni * 8;
                    uint32_t bh[2], bl[2];
                    bh[0] = __float_as_uint(Vh[(c8 + g) * AVP + k0 + t4]);
                    bh[1] = __float_as_uint(Vh[(c8 + g) * AVP + k0 + t4 + 4]);
                    bl[0] = __float_as_uint(Vl[(c8 + g) * AVP + k0 + t4]);
                    bl[1] = __float_as_uint(Vl[(c8 + g) * AVP + k0 + t4 + 4]);
                    mma_tf32_16x8x8(acc_o[ni], ah, bh);
                    mma_tf32_16x8x8(acc_o[ni], ah, bl);
                    mma_tf32_16x8x8(acc_o[ni], al, bh);
                }
            }
        }
    }

    // ---- epilogue: normalize, write O [B,S,H*dh] ----
    {
        const float invA = 1.f / Lr[wm * 16 + g];
        const float invB = 1.f / Lr[wm * 16 + g + 8];
        const int rowA = b * SDIM + qt * 64 + wm * 16 + g;
        const int rowB = rowA + 8;
#pragma unroll
        for (int ni = 0; ni < 8; ni++) {
            const int cc = h * DHDIM + wn * 64 + ni * 8 + t4 * 2;
            float2 lo = {acc_o[ni][0] * invA, acc_o[ni][1] * invA};
            float2 hi = {acc_o[ni][2] * invB, acc_o[ni][3] * invB};
            *(float2*)(O + (size_t)rowA * DDIM + cc) = lo;
            *(float2*)(O + (size_t)rowB * DDIM + cc) = hi;
        }
    }
}

// ---------------------------------------------------------------------------
extern "C" void kernel_launch(void* const* d_in, const int* in_sizes, int n_in,
                              void* d_out, int out_size)
{
    const float* x    = (const float*)d_in[0];
    const float* Wdq  = (const float*)d_in[1];
    const float* Wuq  = (const float*)d_in[2];
    const float* qg   = (const float*)d_in[3];
    const float* qb   = (const float*)d_in[4];
    const float* Wdkv = (const float*)d_in[5];
    const float* Wukv = (const float*)d_in[6];
    const float* kvg  = (const float*)d_in[7];
    const float* kvb  = (const float*)d_in[8];
    const float* Wo   = (const float*)d_in[9];
    float* out = (float*)d_out;

    float *cq, *ckv, *Qb, *KVb, *Ob, *Wt1, *Wt2, *Wt3, *Wt4;
    cudaGetSymbolAddress((void**)&cq,  g_cq);
    cudaGetSymbolAddress((void**)&ckv, g_ckv);
    cudaGetSymbolAddress((void**)&Qb,  g_Q);
    cudaGetSymbolAddress((void**)&KVb, g_KV);
    cudaGetSymbolAddress((void**)&Ob,  g_O);
    cudaGetSymbolAddress((void**)&Wt1, g_Wt1);
    cudaGetSymbolAddress((void**)&Wt2, g_Wt2);
    cudaGetSymbolAddress((void**)&Wt3, g_Wt3);
    cudaGetSymbolAddress((void**)&Wt4, g_Wt4);

    cudaFuncSetAttribute(attn_mma_kernel, cudaFuncAttributeMaxDynamicSharedMemorySize,
                         ATTN_SMEM_BYTES);
    cudaFuncSetAttribute(tgemm_mma, cudaFuncAttributeMaxDynamicSharedMemorySize,
                         TG_SMEM);

    dim3 tb(32, 8);
    transpose_kernel<<<dim3(64,  64), tb>>>(Wdq,  Wt1, DDIM, DDIM);
    transpose_kernel<<<dim3(64,  64), tb>>>(Wdkv, Wt2, DDIM, DDIM);
    transpose_kernel<<<dim3(64,  64), tb>>>(Wuq,  Wt3, DDIM, DDIM);
    transpose_kernel<<<dim3(128, 64), tb>>>(Wukv, Wt4, DDIM, 2 * DDIM);

    dim3 blk(256);

    tgemm_mma<<<dim3(16, 32), blk, TG_SMEM>>>(x, Wt1, cq,  BS_ROWS, DDIM, DDIM);
    tgemm_mma<<<dim3(16, 32), blk, TG_SMEM>>>(x, Wt2, ckv, BS_ROWS, DDIM, DDIM);

    ln_kernel<<<BS_ROWS, 256>>>(cq, qg, qb, nullptr);
    float* ckv_out = (out_size >= 2 * BS_ROWS * DDIM)
                         ? (out + (size_t)BS_ROWS * DDIM) : nullptr;
    ln_kernel<<<BS_ROWS, 256>>>(ckv, kvg, kvb, ckv_out);

    tgemm_mma<<<dim3(16, 32), blk, TG_SMEM>>>(cq,  Wt3, Qb,  BS_ROWS, DDIM,     DDIM);
    tgemm_mma<<<dim3(32, 32), blk, TG_SMEM>>>(ckv, Wt4, KVb, BS_ROWS, 2 * DDIM, DDIM);

    rope_kernel<<<BS_ROWS, 1024>>>(Qb, KVb);

    attn_mma_kernel<<<dim3(32, HDIM, BDIM), blk, ATTN_SMEM_BYTES>>>(Qb, KVb, Ob);

    tgemm_mma<<<dim3(16, 32), blk, TG_SMEM>>>(Ob, Wo, out, BS_ROWS, DDIM, DDIM);
}

// round 7
// speedup vs baseline: 2.5602x; 1.3969x over previous
#include <cuda_runtime.h>
#include <math.h>
#include <stdint.h>

// ---------------------------------------------------------------------------
// MLA prefill: B=2, S=2048, D=2048, H=16, dh=128
// Round 7: GEMM inputs pre-rounded to tf32 at producers; tgemm uses cp.async
// staging (no reg round-trip, no cvt in loop) at 2 CTAs/SM.
// Attention: split-tf32 mma (unchanged except rounded epilogue).
// ---------------------------------------------------------------------------

#define BDIM   2
#define SDIM   2048
#define DDIM   2048
#define HDIM   16
#define DHDIM  128
#define BS_ROWS 4096            // B*S

__device__ float g_cq [BS_ROWS * DDIM];
__device__ float g_ckv[BS_ROWS * DDIM];
__device__ float g_Q  [BS_ROWS * DDIM];
__device__ float g_KV [BS_ROWS * 2 * DDIM];
__device__ float g_O  [BS_ROWS * DDIM];
__device__ float g_xr [BS_ROWS * DDIM];      // tf32-rounded x
__device__ float g_Wt1[DDIM * DDIM];
__device__ float g_Wt2[DDIM * DDIM];
__device__ float g_Wt3[DDIM * DDIM];
__device__ float g_Wt4[2 * DDIM * DDIM];
__device__ float g_Wor[DDIM * DDIM];         // tf32-rounded Wo

__device__ __forceinline__ float tf32_rna(float x) {
    uint32_t u;
    asm("cvt.rna.tf32.f32 %0, %1;" : "=r"(u) : "f"(x));
    return __uint_as_float(u);
}

__device__ __forceinline__ void mma_tf32_16x8x8(float* d, const uint32_t* a,
                                                const uint32_t* b) {
    asm volatile(
        "mma.sync.aligned.m16n8k8.row.col.f32.tf32.tf32.f32 "
        "{%0,%1,%2,%3}, {%4,%5,%6,%7}, {%8,%9}, {%0,%1,%2,%3};\n"
        : "+f"(d[0]), "+f"(d[1]), "+f"(d[2]), "+f"(d[3])
        : "r"(a[0]), "r"(a[1]), "r"(a[2]), "r"(a[3]), "r"(b[0]), "r"(b[1]));
}

__device__ __forceinline__ uint32_t smem_u32(const void* p) {
    uint32_t a;
    asm("{ .reg .u64 t; cvta.to.shared.u64 t, %1; cvt.u32.u64 %0, t; }"
        : "=r"(a) : "l"(p));
    return a;
}
__device__ __forceinline__ void cp16(uint32_t s, const void* g) {
    asm volatile("cp.async.cg.shared.global [%0], [%1], 16;" :: "r"(s), "l"(g));
}
__device__ __forceinline__ void cp_commit() {
    asm volatile("cp.async.commit_group;" ::: "memory");
}
template <int N>
__device__ __forceinline__ void cp_wait() {
    asm volatile("cp.async.wait_group %0;" :: "n"(N) : "memory");
}

// ---------------------------------------------------------------------------
// tf32 tensor-core GEMM: C[M,N] = A[M,K] @ Bt[N,K]^T (both K-major,
// PRE-ROUNDED to tf32). CTA tile 128x128, K chunk 32, cp.async 2-stage,
// 8 warps (2 M x 4 N), each warp 64x32 via m16n8k8. 2 CTAs/SM.
// ---------------------------------------------------------------------------
#define TGP 36
#define TG_TILE (128 * TGP)
#define TG_SMEM (4 * TG_TILE * 4)

__global__ __launch_bounds__(256, 2) void tgemm_mma(
    const float* __restrict__ A, const float* __restrict__ Bt,
    float* __restrict__ C, int M, int N, int K)
{
    extern __shared__ float sm[];
    float* Abuf[2] = {sm, sm + TG_TILE};
    float* Bbuf[2] = {sm + 2 * TG_TILE, sm + 3 * TG_TILE};

    const int tid = threadIdx.x;
    const int wid = tid >> 5, lane = tid & 31;
    const int m0 = blockIdx.y * 128;
    const int n0 = blockIdx.x * 128;

    const int warp_m = wid & 1;
    const int warp_n = wid >> 1;
    const int g  = lane >> 2;
    const int t4 = lane & 3;

    const int lr = tid >> 3;          // 0..31
    const int lc = tid & 7;           // float4 within 32-col chunk

    const uint32_t sAb[2] = {smem_u32(Abuf[0]), smem_u32(Abuf[1])};
    const uint32_t sBb[2] = {smem_u32(Bbuf[0]), smem_u32(Bbuf[1])};
    const uint32_t soff = (uint32_t)(lr * TGP + lc * 4) * 4;   // this thread's base

    float acc[4][4][4];
#pragma unroll
    for (int mi = 0; mi < 4; mi++)
#pragma unroll
        for (int ni = 0; ni < 4; ni++)
#pragma unroll
            for (int q = 0; q < 4; q++) acc[mi][ni][q] = 0.f;

    const int nch = K >> 5;
    const float* Ab = A  + (size_t)(m0 + lr) * K + lc * 4;
    const float* Bb = Bt + (size_t)(n0 + lr) * K + lc * 4;
    const uint32_t rstep = (uint32_t)(32 * TGP * 4);           // 32 rows in smem bytes

    // stage chunk 0
#pragma unroll
    for (int f = 0; f < 4; f++) {
        cp16(sAb[0] + soff + f * rstep, Ab + (size_t)f * 32 * K);
        cp16(sBb[0] + soff + f * rstep, Bb + (size_t)f * 32 * K);
    }
    cp_commit();

    for (int ch = 0; ch < nch; ch++) {
        const int cur = ch & 1, nxt = cur ^ 1;

        if (ch + 1 < nch) {
            const int k0g = (ch + 1) * 32;
#pragma unroll
            for (int f = 0; f < 4; f++) {
                cp16(sAb[nxt] + soff + f * rstep, Ab + (size_t)f * 32 * K + k0g);
                cp16(sBb[nxt] + soff + f * rstep, Bb + (size_t)f * 32 * K + k0g);
            }
            cp_commit();
            cp_wait<1>();
        } else {
            cp_wait<0>();
        }
        __syncthreads();

        const float* As = Abuf[cur];
        const float* Bs = Bbuf[cur];
#pragma unroll
        for (int ks = 0; ks < 4; ks++) {
            const int k0 = ks * 8;
            uint32_t afr[4][4], bfr[4][2];
#pragma unroll
            for (int mi = 0; mi < 4; mi++) {
                const int r16 = warp_m * 64 + mi * 16;
                afr[mi][0] = __float_as_uint(As[(r16 + g)     * TGP + k0 + t4]);
                afr[mi][1] = __float_as_uint(As[(r16 + g + 8) * TGP + k0 + t4]);
                afr[mi][2] = __float_as_uint(As[(r16 + g)     * TGP + k0 + t4 + 4]);
                afr[mi][3] = __float_as_uint(As[(r16 + g + 8) * TGP + k0 + t4 + 4]);
            }
#pragma unroll
            for (int ni = 0; ni < 4; ni++) {
                const int c8 = warp_n * 32 + ni * 8;
                bfr[ni][0] = __float_as_uint(Bs[(c8 + g) * TGP + k0 + t4]);
                bfr[ni][1] = __float_as_uint(Bs[(c8 + g) * TGP + k0 + t4 + 4]);
            }
#pragma unroll
            for (int mi = 0; mi < 4; mi++)
#pragma unroll
                for (int ni = 0; ni < 4; ni++)
                    mma_tf32_16x8x8(acc[mi][ni], afr[mi], bfr[ni]);
        }
        __syncthreads();
    }

#pragma unroll
    for (int mi = 0; mi < 4; mi++) {
        const int r16 = m0 + warp_m * 64 + mi * 16;
#pragma unroll
        for (int ni = 0; ni < 4; ni++) {
            const int cc = n0 + warp_n * 32 + ni * 8 + t4 * 2;
            float2 lo = {acc[mi][ni][0], acc[mi][ni][1]};
            float2 hi = {acc[mi][ni][2], acc[mi][ni][3]};
            *(float2*)(C + (size_t)(r16 + g)     * N + cc) = lo;
            *(float2*)(C + (size_t)(r16 + g + 8) * N + cc) = hi;
        }
    }
}

// ---------------------------------------------------------------------------
// 32x32 tiled transpose with tf32 rounding: Wt[C,R] = rna(W[R,C]^T)
// ---------------------------------------------------------------------------
__global__ void transpose_kernel(const float* __restrict__ W, float* __restrict__ Wt,
                                 int R, int C)
{
    __shared__ float t[32][33];
    const int c0 = blockIdx.x * 32, r0 = blockIdx.y * 32;
    const int x = threadIdx.x, y = threadIdx.y;
#pragma unroll
    for (int j = 0; j < 32; j += 8)
        t[y + j][x] = tf32_rna(W[(size_t)(r0 + y + j) * C + c0 + x]);
    __syncthreads();
#pragma unroll
    for (int j = 0; j < 32; j += 8)
        Wt[(size_t)(c0 + y + j) * R + r0 + x] = t[x][y + j];
}

// elementwise tf32 rounding (for x and Wo)
__global__ void round_kernel(const float* __restrict__ in, float* __restrict__ out,
                             int n4)
{
    const int i = blockIdx.x * blockDim.x + threadIdx.x;
    if (i < n4) {
        float4 v = ((const float4*)in)[i];
        v.x = tf32_rna(v.x); v.y = tf32_rna(v.y);
        v.z = tf32_rna(v.z); v.w = tf32_rna(v.w);
        ((float4*)out)[i] = v;
    }
}

// ---------------------------------------------------------------------------
// LayerNorm: writes tf32-rounded result in place (GEMM input); out2 (harness
// output) gets the full-precision value.
// ---------------------------------------------------------------------------
__global__ void ln_kernel(float* __restrict__ X, const float* __restrict__ gamma,
                          const float* __restrict__ beta, float* __restrict__ out2)
{
    const int row = blockIdx.x;
    const int tid = threadIdx.x;
    float* xr = X + (size_t)row * DDIM;

    float v[8];
    float s = 0.f, sq = 0.f;
#pragma unroll
    for (int j = 0; j < 8; j++) {
        v[j] = xr[tid + j * 256];
        s  += v[j];
        sq += v[j] * v[j];
    }

    __shared__ float red[64];
#pragma unroll
    for (int off = 16; off; off >>= 1) {
        s  += __shfl_xor_sync(0xffffffffu, s,  off);
        sq += __shfl_xor_sync(0xffffffffu, sq, off);
    }
    const int wid = tid >> 5, lane = tid & 31;
    if (lane == 0) { red[wid] = s; red[32 + wid] = sq; }
    __syncthreads();
    if (wid == 0) {
        s  = (lane < 8) ? red[lane]      : 0.f;
        sq = (lane < 8) ? red[32 + lane] : 0.f;
#pragma unroll
        for (int off = 4; off; off >>= 1) {
            s  += __shfl_xor_sync(0xffffffffu, s,  off);
            sq += __shfl_xor_sync(0xffffffffu, sq, off);
        }
        if (lane == 0) { red[0] = s; red[1] = sq; }
    }
    __syncthreads();

    const float mean = red[0] * (1.f / DDIM);
    const float var  = red[1] * (1.f / DDIM) - mean * mean;
    const float rstd = rsqrtf(var + 1e-5f);

#pragma unroll
    for (int j = 0; j < 8; j++) {
        const int c = tid + j * 256;
        float y = (v[j] - mean) * rstd * gamma[c] + beta[c];
        if (out2) out2[(size_t)row * DDIM + c] = y;
        xr[c] = tf32_rna(y);
    }
}

// ---------------------------------------------------------------------------
__global__ void rope_kernel(float* __restrict__ Q, float* __restrict__ KV)
{
    const int row = blockIdx.x;
    const int t   = row & (SDIM - 1);
    const int tid = threadIdx.x;
    const int h   = tid >> 6;
    const int i   = tid & 63;

    const float freq = (float)exp(-(double)i * (log(10000.0) / 64.0));
    const float ang  = (float)t * freq;
    float sn, cs;
    sincosf(ang, &sn, &cs);

    const size_t qb = (size_t)row * DDIM + h * DHDIM + i;
    float x1 = Q[qb], x2 = Q[qb + 64];
    Q[qb]      = x1 * cs - x2 * sn;
    Q[qb + 64] = x2 * cs + x1 * sn;

    const size_t kb = (size_t)row * (2 * DDIM) + h * DHDIM + i;
    float y1 = KV[kb], y2 = KV[kb + 64];
    KV[kb]      = y1 * cs - y2 * sn;
    KV[kb + 64] = y2 * cs + y1 * sn;
}

// ---------------------------------------------------------------------------
// Flash attention with split-tf32 tensor cores (unchanged from R6 except the
// epilogue rounds O to tf32 — it feeds the final GEMM).
// ---------------------------------------------------------------------------
#define AQP 132
#define AVP 68
#define OFF_QH 0
#define OFF_QL 8448
#define OFF_KH 16896
#define OFF_KL 25344
#define OFF_VH 33792
#define OFF_VL 42496
#define OFF_PS 51200
#define OFF_M  55552
#define OFF_L  55616
#define OFF_C  55680
#define ATTN_SMEM_FLOATS 55744
#define ATTN_SMEM_BYTES  (ATTN_SMEM_FLOATS * 4)

__global__ __launch_bounds__(256, 1) void attn_mma_kernel(
    const float* __restrict__ Q, const float* __restrict__ KV, float* __restrict__ O)
{
    extern __shared__ float smx[];
    float* Qh = smx + OFF_QH;
    float* Ql = smx + OFF_QL;
    float* Kh = smx + OFF_KH;
    float* Kl = smx + OFF_KL;
    float* Vh = smx + OFF_VH;
    float* Vl = smx + OFF_VL;
    float* Ps = smx + OFF_PS;
    float* Mr = smx + OFF_M;
    float* Lr = smx + OFF_L;
    float* Cr = smx + OFF_C;

    const int qt = blockIdx.x, h = blockIdx.y, b = blockIdx.z;
    const int tid = threadIdx.x;
    const int wid = tid >> 5, lane = tid & 31;
    const int g = lane >> 2, t4 = lane & 3;
    const float scale = 0.088388347648318447f;

    const int wm = wid & 3;
    const int wn = wid >> 2;

    {
        const int r  = tid >> 2;
        const int c0 = tid & 3;
        const float* gq = Q + (size_t)(b * SDIM + qt * 64 + r) * DDIM + h * DHDIM;
#pragma unroll
        for (int rep = 0; rep < 8; rep++) {
            const int c4 = c0 + rep * 4;
            float4 v = *(const float4*)(gq + c4 * 4);
            float vv[4] = {v.x, v.y, v.z, v.w};
#pragma unroll
            for (int j = 0; j < 4; j++) {
                const int col = c4 * 4 + j;
                float hi = tf32_rna(vv[j]);
                Qh[r * AQP + col] = hi;
                Ql[r * AQP + col] = tf32_rna(vv[j] - hi);
            }
        }
        if (tid < 64) { Mr[tid] = -1e30f; Lr[tid] = 0.f; }
    }

    float acc_o[8][4];
#pragma unroll
    for (int ni = 0; ni < 8; ni++)
#pragma unroll
        for (int q = 0; q < 4; q++) acc_o[ni][q] = 0.f;

    for (int kt = 0; kt <= qt; kt++) {
        __syncthreads();

        {
            const int r  = tid >> 2;
            const int c0 = tid & 3;
            const float* gk = KV + (size_t)(b * SDIM + kt * 64 + r) * (2 * DDIM) + h * DHDIM;
            const float* gv = gk + DDIM;
#pragma unroll
            for (int rep = 0; rep < 8; rep++) {
                const int c4 = c0 + rep * 4;
                float4 kv4 = *(const float4*)(gk + c4 * 4);
                float4 vv4 = *(const float4*)(gv + c4 * 4);
                float kk[4] = {kv4.x, kv4.y, kv4.z, kv4.w};
                float vv[4] = {vv4.x, vv4.y, vv4.z, vv4.w};
#pragma unroll
                for (int j = 0; j < 4; j++) {
                    const int col = c4 * 4 + j;
                    float khi = tf32_rna(kk[j]);
                    Kh[r * AQP + col] = khi;
                    Kl[r * AQP + col] = tf32_rna(kk[j] - khi);
                    float vhi = tf32_rna(vv[j]);
                    Vh[col * AVP + r] = vhi;
                    Vl[col * AVP + r] = tf32_rna(vv[j] - vhi);
                }
            }
        }
        __syncthreads();

        float sacc[4][4];
#pragma unroll
        for (int ni = 0; ni < 4; ni++)
#pragma unroll
            for (int q = 0; q < 4; q++) sacc[ni][q] = 0.f;

#pragma unroll
        for (int ch = 0; ch < 16; ch++) {
            const int k0 = ch * 8;
            uint32_t ah[4], al[4];
            const int r0 = wm * 16;
            ah[0] = __float_as_uint(Qh[(r0 + g)     * AQP + k0 + t4]);
            ah[1] = __float_as_uint(Qh[(r0 + g + 8) * AQP + k0 + t4]);
            ah[2] = __float_as_uint(Qh[(r0 + g)     * AQP + k0 + t4 + 4]);
            ah[3] = __float_as_uint(Qh[(r0 + g + 8) * AQP + k0 + t4 + 4]);
            al[0] = __float_as_uint(Ql[(r0 + g)     * AQP + k0 + t4]);
            al[1] = __float_as_uint(Ql[(r0 + g + 8) * AQP + k0 + t4]);
            al[2] = __float_as_uint(Ql[(r0 + g)     * AQP + k0 + t4 + 4]);
            al[3] = __float_as_uint(Ql[(r0 + g + 8) * AQP + k0 + t4 + 4]);
#pragma unroll
            for (int ni = 0; ni < 4; ni++) {
                const int c8 = wn * 32 + ni * 8;
                uint32_t bh[2], bl[2];
                bh[0] = __float_as_uint(Kh[(c8 + g) * AQP + k0 + t4]);
                bh[1] = __float_as_uint(Kh[(c8 + g) * AQP + k0 + t4 + 4]);
                bl[0] = __float_as_uint(Kl[(c8 + g) * AQP + k0 + t4]);
                bl[1] = __float_as_uint(Kl[(c8 + g) * AQP + k0 + t4 + 4]);
                mma_tf32_16x8x8(sacc[ni], ah, bh);
                mma_tf32_16x8x8(sacc[ni], ah, bl);
                mma_tf32_16x8x8(sacc[ni], al, bh);
            }
        }

        const bool diag = (kt == qt);
#pragma unroll
        for (int ni = 0; ni < 4; ni++) {
            const int c0 = wn * 32 + ni * 8 + t4 * 2;
            const int rA = wm * 16 + g, rB = rA + 8;
            float s0 = sacc[ni][0] * scale, s1 = sacc[ni][1] * scale;
            float s2 = sacc[ni][2] * scale, s3 = sacc[ni][3] * scale;
            if (diag) {
                if (c0     > rA) s0 = -1e30f;
                if (c0 + 1 > rA) s1 = -1e30f;
                if (c0     > rB) s2 = -1e30f;
                if (c0 + 1 > rB) s3 = -1e30f;
            }
            Ps[rA * AVP + c0]     = s0;
            Ps[rA * AVP + c0 + 1] = s1;
            Ps[rB * AVP + c0]     = s2;
            Ps[rB * AVP + c0 + 1] = s3;
        }
        __syncthreads();

        {
            const int row = tid >> 2;
            const int q4  = tid & 3;
            float* pr = Ps + row * AVP + q4 * 16;
            float lmax = -1e30f;
#pragma unroll
            for (int j = 0; j < 16; j++) lmax = fmaxf(lmax, pr[j]);
            lmax = fmaxf(lmax, __shfl_xor_sync(0xffffffffu, lmax, 1));
            lmax = fmaxf(lmax, __shfl_xor_sync(0xffffffffu, lmax, 2));
            const float mold = Mr[row];
            const float mnew = fmaxf(mold, lmax);
            float lsum = 0.f;
#pragma unroll
            for (int j = 0; j < 16; j++) {
                float p = expf(pr[j] - mnew);
                pr[j] = p;
                lsum += p;
            }
            lsum += __shfl_xor_sync(0xffffffffu, lsum, 1);
            lsum += __shfl_xor_sync(0xffffffffu, lsum, 2);
            if (q4 == 0) {
                const float corr = expf(mold - mnew);
                Cr[row] = corr;
                Lr[row] = Lr[row] * corr + lsum;
                Mr[row] = mnew;
            }
        }
        __syncthreads();

        {
            const float cg  = Cr[wm * 16 + g];
            const float cg8 = Cr[wm * 16 + g + 8];
#pragma unroll
            for (int ni = 0; ni < 8; ni++) {
                acc_o[ni][0] *= cg;  acc_o[ni][1] *= cg;
                acc_o[ni][2] *= cg8; acc_o[ni][3] *= cg8;
            }
#pragma unroll
            for (int ch = 0; ch < 8; ch++) {
                const int k0 = ch * 8;
                const int r0 = wm * 16;
                float p0 = Ps[(r0 + g)     * AVP + k0 + t4];
                float p1 = Ps[(r0 + g + 8) * AVP + k0 + t4];
                float p2 = Ps[(r0 + g)     * AVP + k0 + t4 + 4];
                float p3 = Ps[(r0 + g + 8) * AVP + k0 + t4 + 4];
                uint32_t ah[4], al[4];
                float h0 = tf32_rna(p0), h1 = tf32_rna(p1);
                float h2 = tf32_rna(p2), h3 = tf32_rna(p3);
                ah[0] = __float_as_uint(h0); ah[1] = __float_as_uint(h1);
                ah[2] = __float_as_uint(h2); ah[3] = __float_as_uint(h3);
                al[0] = __float_as_uint(tf32_rna(p0 - h0));
                al[1] = __float_as_uint(tf32_rna(p1 - h1));
                al[2] = __float_as_uint(tf32_rna(p2 - h2));
                al[3] = __float_as_uint(tf32_rna(p3 - h3));
#pragma unroll
                for (int ni = 0; ni < 8; ni++) {
                    const int c8 = wn * 64 + ni * 8;
                    uint32_t bh[2], bl[2];
                    bh[0] = __float_as_uint(Vh[(c8 + g) * AVP + k0 + t4]);
                    bh[1] = __float_as_uint(Vh[(c8 + g) * AVP + k0 + t4 + 4]);
                    bl[0] = __float_as_uint(Vl[(c8 + g) * AVP + k0 + t4]);
                    bl[1] = __float_as_uint(Vl[(c8 + g) * AVP + k0 + t4 + 4]);
                    mma_tf32_16x8x8(acc_o[ni], ah, bh);
                    mma_tf32_16x8x8(acc_o[ni], ah, bl);
                    mma_tf32_16x8x8(acc_o[ni], al, bh);
                }
            }
        }
    }

    // epilogue: normalize, round to tf32 (feeds final GEMM), write O
    {
        const float invA = 1.f / Lr[wm * 16 + g];
        const float invB = 1.f / Lr[wm * 16 + g + 8];
        const int rowA = b * SDIM + qt * 64 + wm * 16 + g;
        const int rowB = rowA + 8;
#pragma unroll
        for (int ni = 0; ni < 8; ni++) {
            const int cc = h * DHDIM + wn * 64 + ni * 8 + t4 * 2;
            float2 lo = {tf32_rna(acc_o[ni][0] * invA), tf32_rna(acc_o[ni][1] * invA)};
            float2 hi = {tf32_rna(acc_o[ni][2] * invB), tf32_rna(acc_o[ni][3] * invB)};
            *(float2*)(O + (size_t)rowA * DDIM + cc) = lo;
            *(float2*)(O + (size_t)rowB * DDIM + cc) = hi;
        }
    }
}

// ---------------------------------------------------------------------------
extern "C" void kernel_launch(void* const* d_in, const int* in_sizes, int n_in,
                              void* d_out, int out_size)
{
    const float* x    = (const float*)d_in[0];
    const float* Wdq  = (const float*)d_in[1];
    const float* Wuq  = (const float*)d_in[2];
    const float* qg   = (const float*)d_in[3];
    const float* qb   = (const float*)d_in[4];
    const float* Wdkv = (const float*)d_in[5];
    const float* Wukv = (const float*)d_in[6];
    const float* kvg  = (const float*)d_in[7];
    const float* kvb  = (const float*)d_in[8];
    const float* Wo   = (const float*)d_in[9];
    float* out = (float*)d_out;

    float *cq, *ckv, *Qb, *KVb, *Ob, *xr, *Wt1, *Wt2, *Wt3, *Wt4, *Wor;
    cudaGetSymbolAddress((void**)&cq,  g_cq);
    cudaGetSymbolAddress((void**)&ckv, g_ckv);
    cudaGetSymbolAddress((void**)&Qb,  g_Q);
    cudaGetSymbolAddress((void**)&KVb, g_KV);
    cudaGetSymbolAddress((void**)&Ob,  g_O);
    cudaGetSymbolAddress((void**)&xr,  g_xr);
    cudaGetSymbolAddress((void**)&Wt1, g_Wt1);
    cudaGetSymbolAddress((void**)&Wt2, g_Wt2);
    cudaGetSymbolAddress((void**)&Wt3, g_Wt3);
    cudaGetSymbolAddress((void**)&Wt4, g_Wt4);
    cudaGetSymbolAddress((void**)&Wor, g_Wor);

    cudaFuncSetAttribute(attn_mma_kernel, cudaFuncAttributeMaxDynamicSharedMemorySize,
                         ATTN_SMEM_BYTES);
    cudaFuncSetAttribute(tgemm_mma, cudaFuncAttributeMaxDynamicSharedMemorySize,
                         TG_SMEM);

    dim3 tb(32, 8);
    transpose_kernel<<<dim3(64,  64), tb>>>(Wdq,  Wt1, DDIM, DDIM);
    transpose_kernel<<<dim3(64,  64), tb>>>(Wdkv, Wt2, DDIM, DDIM);
    transpose_kernel<<<dim3(64,  64), tb>>>(Wuq,  Wt3, DDIM, DDIM);
    transpose_kernel<<<dim3(128, 64), tb>>>(Wukv, Wt4, DDIM, 2 * DDIM);
    round_kernel<<<(BS_ROWS * DDIM / 4 + 255) / 256, 256>>>(x,  xr,  BS_ROWS * DDIM / 4);
    round_kernel<<<(DDIM * DDIM / 4 + 255) / 256, 256>>>(Wo, Wor, DDIM * DDIM / 4);

    dim3 blk(256);

    tgemm_mma<<<dim3(16, 32), blk, TG_SMEM>>>(xr, Wt1, cq,  BS_ROWS, DDIM, DDIM);
    tgemm_mma<<<dim3(16, 32), blk, TG_SMEM>>>(xr, Wt2, ckv, BS_ROWS, DDIM, DDIM);

    ln_kernel<<<BS_ROWS, 256>>>(cq, qg, qb, nullptr);
    float* ckv_out = (out_size >= 2 * BS_ROWS * DDIM)
                         ? (out + (size_t)BS_ROWS * DDIM) : nullptr;
    ln_kernel<<<BS_ROWS, 256>>>(ckv, kvg, kvb, ckv_out);

    tgemm_mma<<<dim3(16, 32), blk, TG_SMEM>>>(cq,  Wt3, Qb,  BS_ROWS, DDIM,     DDIM);
    tgemm_mma<<<dim3(32, 32), blk, TG_SMEM>>>(ckv, Wt4, KVb, BS_ROWS, 2 * DDIM, DDIM);

    rope_kernel<<<BS_ROWS, 1024>>>(Qb, KVb);

    attn_mma_kernel<<<dim3(32, HDIM, BDIM), blk, ATTN_SMEM_BYTES>>>(Qb, KVb, Ob);

    tgemm_mma<<<dim3(16, 32), blk, TG_SMEM>>>(Ob, Wor, out, BS_ROWS, DDIM, DDIM);
}

// round 8
// speedup vs baseline: 2.7769x; 1.0846x over previous
#include <cuda_runtime.h>
#include <math.h>
#include <stdint.h>

// ---------------------------------------------------------------------------
// MLA prefill: B=2, S=2048, D=2048, H=16, dh=128
// Round 8: GEMM v2 — CTA 128x256, 64x64 warp tiles (crossbar/mma balanced),
// 3-stage cp.async ring w/ single sync per chunk, fused down-projection GEMM
// (N=4096) + merged LN launch. Attention unchanged (split-tf32 mma).
// ---------------------------------------------------------------------------

#define BDIM   2
#define SDIM   2048
#define DDIM   2048
#define HDIM   16
#define DHDIM  128
#define BS_ROWS 4096            // B*S

__device__ float g_c12[BS_ROWS * 2 * DDIM];  // [row][cq(2048) | ckv(2048)]
__device__ float g_Q  [BS_ROWS * DDIM];
__device__ float g_KV [BS_ROWS * 2 * DDIM];
__device__ float g_O  [BS_ROWS * DDIM];
__device__ float g_xr [BS_ROWS * DDIM];      // tf32-rounded x
__device__ float g_Wt12[2 * DDIM * DDIM];    // [Wdq^T ; Wdkv^T] concat rows
__device__ float g_Wt3[DDIM * DDIM];         // Wuq^T
__device__ float g_Wt4[2 * DDIM * DDIM];     // Wukv^T
__device__ float g_Wor[DDIM * DDIM];         // tf32-rounded Wo

__device__ __forceinline__ float tf32_rna(float x) {
    uint32_t u;
    asm("cvt.rna.tf32.f32 %0, %1;" : "=r"(u) : "f"(x));
    return __uint_as_float(u);
}

__device__ __forceinline__ void mma_tf32_16x8x8(float* d, const uint32_t* a,
                                                const uint32_t* b) {
    asm volatile(
        "mma.sync.aligned.m16n8k8.row.col.f32.tf32.tf32.f32 "
        "{%0,%1,%2,%3}, {%4,%5,%6,%7}, {%8,%9}, {%0,%1,%2,%3};\n"
        : "+f"(d[0]), "+f"(d[1]), "+f"(d[2]), "+f"(d[3])
        : "r"(a[0]), "r"(a[1]), "r"(a[2]), "r"(a[3]), "r"(b[0]), "r"(b[1]));
}

__device__ __forceinline__ uint32_t smem_u32(const void* p) {
    uint32_t a;
    asm("{ .reg .u64 t; cvta.to.shared.u64 t, %1; cvt.u32.u64 %0, t; }"
        : "=r"(a) : "l"(p));
    return a;
}
__device__ __forceinline__ void cp16(uint32_t s, const void* g) {
    asm volatile("cp.async.cg.shared.global [%0], [%1], 16;" :: "r"(s), "l"(g));
}
__device__ __forceinline__ void cp_commit() {
    asm volatile("cp.async.commit_group;" ::: "memory");
}
template <int N>
__device__ __forceinline__ void cp_wait() {
    asm volatile("cp.async.wait_group %0;" :: "n"(N) : "memory");
}

// ---------------------------------------------------------------------------
// tf32 GEMM v2: C[M,N] = A[M,K] @ Bt[N,K]^T, inputs pre-rounded to tf32.
// CTA tile 128(M) x 256(N), K chunk 32, 3-stage cp.async ring (1 sync/chunk).
// 8 warps as 2(M) x 4(N), each warp 64x64 via m16n8k8. Strides lda/ldb/ldc.
// ---------------------------------------------------------------------------
#define TGP 36
#define TG_AFL (128 * TGP)                   // A tile floats
#define TG_STG ((128 + 256) * TGP)           // floats per stage (A then B)
#define TG_SMEM (3 * TG_STG * 4)             // bytes

__global__ __launch_bounds__(256, 1) void tgemm_mma(
    const float* __restrict__ A, int lda,
    const float* __restrict__ Bt, int ldb,
    float* __restrict__ C, int ldc,
    int M, int N, int K)
{
    extern __shared__ float sm[];

    const int tid = threadIdx.x;
    const int wid = tid >> 5, lane = tid & 31;
    const int m0 = blockIdx.y * 128;
    const int n0 = blockIdx.x * 256;

    const int warp_m = wid & 1;        // 64-row half
    const int warp_n = wid >> 1;       // 64-col quarter
    const int g  = lane >> 2;
    const int t4 = lane & 3;

    const int lr = tid >> 3;           // 0..31
    const int lc = tid & 7;            // float4 within 32-col chunk

    float acc[4][8][4];
#pragma unroll
    for (int mi = 0; mi < 4; mi++)
#pragma unroll
        for (int ni = 0; ni < 8; ni++)
#pragma unroll
            for (int q = 0; q < 4; q++) acc[mi][ni][q] = 0.f;

    const int nch = K >> 5;
    const float* Ab = A  + (size_t)(m0 + lr) * lda + lc * 4;
    const float* Bb = Bt + (size_t)(n0 + lr) * ldb + lc * 4;

    const uint32_t sbase = smem_u32(sm);
    const uint32_t soff  = (uint32_t)(lr * TGP + lc * 4) * 4;
    const uint32_t rstep = (uint32_t)(32 * TGP * 4);

    // prologue: stage chunks 0 and 1
#pragma unroll
    for (int p = 0; p < 2; p++) {
        const uint32_t sb = sbase + p * (TG_STG * 4);
        const int k0g = p * 32;
#pragma unroll
        for (int f = 0; f < 4; f++)
            cp16(sb + soff + f * rstep, Ab + (size_t)f * 32 * lda + k0g);
#pragma unroll
        for (int f = 0; f < 8; f++)
            cp16(sb + (TG_AFL * 4) + soff + f * rstep, Bb + (size_t)f * 32 * ldb + k0g);
        cp_commit();
    }

    for (int ch = 0; ch < nch; ch++) {
        cp_wait<1>();
        __syncthreads();

        // issue chunk ch+2 into ring slot (ch+2)%3 (that slot was consumed by
        // chunk ch-1, finished before this barrier)
        if (ch + 2 < nch) {
            const uint32_t sb = sbase + ((ch + 2) % 3) * (TG_STG * 4);
            const int k0g = (ch + 2) * 32;
#pragma unroll
            for (int f = 0; f < 4; f++)
                cp16(sb + soff + f * rstep, Ab + (size_t)f * 32 * lda + k0g);
#pragma unroll
            for (int f = 0; f < 8; f++)
                cp16(sb + (TG_AFL * 4) + soff + f * rstep, Bb + (size_t)f * 32 * ldb + k0g);
        }
        cp_commit();   // always commit (possibly empty) to keep group count uniform

        const float* As = sm + (ch % 3) * TG_STG;
        const float* Bs = As + TG_AFL;
#pragma unroll
        for (int ks = 0; ks < 4; ks++) {
            const int k0 = ks * 8;
            uint32_t afr[4][4], bfr[8][2];
#pragma unroll
            for (int mi = 0; mi < 4; mi++) {
                const int r16 = warp_m * 64 + mi * 16;
                afr[mi][0] = __float_as_uint(As[(r16 + g)     * TGP + k0 + t4]);
                afr[mi][1] = __float_as_uint(As[(r16 + g + 8) * TGP + k0 + t4]);
                afr[mi][2] = __float_as_uint(As[(r16 + g)     * TGP + k0 + t4 + 4]);
                afr[mi][3] = __float_as_uint(As[(r16 + g + 8) * TGP + k0 + t4 + 4]);
            }
#pragma unroll
            for (int ni = 0; ni < 8; ni++) {
                const int c8 = warp_n * 64 + ni * 8;
                bfr[ni][0] = __float_as_uint(Bs[(c8 + g) * TGP + k0 + t4]);
                bfr[ni][1] = __float_as_uint(Bs[(c8 + g) * TGP + k0 + t4 + 4]);
            }
#pragma unroll
            for (int mi = 0; mi < 4; mi++)
#pragma unroll
                for (int ni = 0; ni < 8; ni++)
                    mma_tf32_16x8x8(acc[mi][ni], afr[mi], bfr[ni]);
        }
    }

#pragma unroll
    for (int mi = 0; mi < 4; mi++) {
        const int r16 = m0 + warp_m * 64 + mi * 16;
#pragma unroll
        for (int ni = 0; ni < 8; ni++) {
            const int cc = n0 + warp_n * 64 + ni * 8 + t4 * 2;
            float2 lo = {acc[mi][ni][0], acc[mi][ni][1]};
            float2 hi = {acc[mi][ni][2], acc[mi][ni][3]};
            *(float2*)(C + (size_t)(r16 + g)     * ldc + cc) = lo;
            *(float2*)(C + (size_t)(r16 + g + 8) * ldc + cc) = hi;
        }
    }
}

// ---------------------------------------------------------------------------
// 32x32 tiled transpose with tf32 rounding: Wt[C,R] = rna(W[R,C]^T)
// ---------------------------------------------------------------------------
__global__ void transpose_kernel(const float* __restrict__ W, float* __restrict__ Wt,
                                 int R, int C)
{
    __shared__ float t[32][33];
    const int c0 = blockIdx.x * 32, r0 = blockIdx.y * 32;
    const int x = threadIdx.x, y = threadIdx.y;
#pragma unroll
    for (int j = 0; j < 32; j += 8)
        t[y + j][x] = tf32_rna(W[(size_t)(r0 + y + j) * C + c0 + x]);
    __syncthreads();
#pragma unroll
    for (int j = 0; j < 32; j += 8)
        Wt[(size_t)(c0 + y + j) * R + r0 + x] = t[x][y + j];
}

__global__ void round_kernel(const float* __restrict__ in, float* __restrict__ out,
                             int n4)
{
    const int i = blockIdx.x * blockDim.x + threadIdx.x;
    if (i < n4) {
        float4 v = ((const float4*)in)[i];
        v.x = tf32_rna(v.x); v.y = tf32_rna(v.y);
        v.z = tf32_rna(v.z); v.w = tf32_rna(v.w);
        ((float4*)out)[i] = v;
    }
}

// ---------------------------------------------------------------------------
// Merged LayerNorm over both halves of C12 [row][cq|ckv] (stride 4096).
// blockIdx.y: 0 = cq (no mirror), 1 = ckv (mirrors full-precision to out2).
// Writes tf32-rounded result in place (feeds next GEMM).
// ---------------------------------------------------------------------------
__global__ void ln2_kernel(float* __restrict__ C12,
                           const float* __restrict__ g1, const float* __restrict__ b1,
                           const float* __restrict__ g2, const float* __restrict__ b2,
                           float* __restrict__ out2)
{
    const int row  = blockIdx.x;
    const int part = blockIdx.y;
    const int tid  = threadIdx.x;
    float* xr = C12 + (size_t)row * (2 * DDIM) + part * DDIM;
    const float* gamma = part ? g2 : g1;
    const float* beta  = part ? b2 : b1;

    float v[8];
    float s = 0.f, sq = 0.f;
#pragma unroll
    for (int j = 0; j < 8; j++) {
        v[j] = xr[tid + j * 256];
        s  += v[j];
        sq += v[j] * v[j];
    }

    __shared__ float red[64];
#pragma unroll
    for (int off = 16; off; off >>= 1) {
        s  += __shfl_xor_sync(0xffffffffu, s,  off);
        sq += __shfl_xor_sync(0xffffffffu, sq, off);
    }
    const int wid = tid >> 5, lane = tid & 31;
    if (lane == 0) { red[wid] = s; red[32 + wid] = sq; }
    __syncthreads();
    if (wid == 0) {
        s  = (lane < 8) ? red[lane]      : 0.f;
        sq = (lane < 8) ? red[32 + lane] : 0.f;
#pragma unroll
        for (int off = 4; off; off >>= 1) {
            s  += __shfl_xor_sync(0xffffffffu, s,  off);
            sq += __shfl_xor_sync(0xffffffffu, sq, off);
        }
        if (lane == 0) { red[0] = s; red[1] = sq; }
    }
    __syncthreads();

    const float mean = red[0] * (1.f / DDIM);
    const float var  = red[1] * (1.f / DDIM) - mean * mean;
    const float rstd = rsqrtf(var + 1e-5f);

#pragma unroll
    for (int j = 0; j < 8; j++) {
        const int c = tid + j * 256;
        float y = (v[j] - mean) * rstd * gamma[c] + beta[c];
        if (part && out2) out2[(size_t)row * DDIM + c] = y;
        xr[c] = tf32_rna(y);
    }
}

// ---------------------------------------------------------------------------
__global__ void rope_kernel(float* __restrict__ Q, float* __restrict__ KV)
{
    const int row = blockIdx.x;
    const int t   = row & (SDIM - 1);
    const int tid = threadIdx.x;
    const int h   = tid >> 6;
    const int i   = tid & 63;

    const float freq = (float)exp(-(double)i * (log(10000.0) / 64.0));
    const float ang  = (float)t * freq;
    float sn, cs;
    sincosf(ang, &sn, &cs);

    const size_t qb = (size_t)row * DDIM + h * DHDIM + i;
    float x1 = Q[qb], x2 = Q[qb + 64];
    Q[qb]      = x1 * cs - x2 * sn;
    Q[qb + 64] = x2 * cs + x1 * sn;

    const size_t kb = (size_t)row * (2 * DDIM) + h * DHDIM + i;
    float y1 = KV[kb], y2 = KV[kb + 64];
    KV[kb]      = y1 * cs - y2 * sn;
    KV[kb + 64] = y2 * cs + y1 * sn;
}

// ---------------------------------------------------------------------------
// Flash attention with split-tf32 tensor cores (unchanged from R7).
// ---------------------------------------------------------------------------
#define AQP 132
#define AVP 68
#define OFF_QH 0
#define OFF_QL 8448
#define OFF_KH 16896
#define OFF_KL 25344
#define OFF_VH 33792
#define OFF_VL 42496
#define OFF_PS 51200
#define OFF_M  55552
#define OFF_L  55616
#define OFF_C  55680
#define ATTN_SMEM_FLOATS 55744
#define ATTN_SMEM_BYTES  (ATTN_SMEM_FLOATS * 4)

__global__ __launch_bounds__(256, 1) void attn_mma_kernel(
    const float* __restrict__ Q, const float* __restrict__ KV, float* __restrict__ O)
{
    extern __shared__ float smx[];
    float* Qh = smx + OFF_QH;
    float* Ql = smx + OFF_QL;
    float* Kh = smx + OFF_KH;
    float* Kl = smx + OFF_KL;
    float* Vh = smx + OFF_VH;
    float* Vl = smx + OFF_VL;
    float* Ps = smx + OFF_PS;
    float* Mr = smx + OFF_M;
    float* Lr = smx + OFF_L;
    float* Cr = smx + OFF_C;

    const int qt = blockIdx.x, h = blockIdx.y, b = blockIdx.z;
    const int tid = threadIdx.x;
    const int wid = tid >> 5, lane = tid & 31;
    const int g = lane >> 2, t4 = lane & 3;
    const float scale = 0.088388347648318447f;

    const int wm = wid & 3;
    const int wn = wid >> 2;

    {
        const int r  = tid >> 2;
        const int c0 = tid & 3;
        const float* gq = Q + (size_t)(b * SDIM + qt * 64 + r) * DDIM + h * DHDIM;
#pragma unroll
        for (int rep = 0; rep < 8; rep++) {
            const int c4 = c0 + rep * 4;
            float4 v = *(const float4*)(gq + c4 * 4);
            float vv[4] = {v.x, v.y, v.z, v.w};
#pragma unroll
            for (int j = 0; j < 4; j++) {
                const int col = c4 * 4 + j;
                float hi = tf32_rna(vv[j]);
                Qh[r * AQP + col] = hi;
                Ql[r * AQP + col] = tf32_rna(vv[j] - hi);
            }
        }
        if (tid < 64) { Mr[tid] = -1e30f; Lr[tid] = 0.f; }
    }

    float acc_o[8][4];
#pragma unroll
    for (int ni = 0; ni < 8; ni++)
#pragma unroll
        for (int q = 0; q < 4; q++) acc_o[ni][q] = 0.f;

    for (int kt = 0; kt <= qt; kt++) {
        __syncthreads();

        {
            const int r  = tid >> 2;
            const int c0 = tid & 3;
            const float* gk = KV + (size_t)(b * SDIM + kt * 64 + r) * (2 * DDIM) + h * DHDIM;
            const float* gv = gk + DDIM;
#pragma unroll
            for (int rep = 0; rep < 8; rep++) {
                const int c4 = c0 + rep * 4;
                float4 kv4 = *(const float4*)(gk + c4 * 4);
                float4 vv4 = *(const float4*)(gv + c4 * 4);
                float kk[4] = {kv4.x, kv4.y, kv4.z, kv4.w};
                float vv[4] = {vv4.x, vv4.y, vv4.z, vv4.w};
#pragma unroll
                for (int j = 0; j < 4; j++) {
                    const int col = c4 * 4 + j;
                    float khi = tf32_rna(kk[j]);
                    Kh[r * AQP + col] = khi;
                    Kl[r * AQP + col] = tf32_rna(kk[j] - khi);
                    float vhi = tf32_rna(vv[j]);
                    Vh[col * AVP + r] = vhi;
                    Vl[col * AVP + r] = tf32_rna(vv[j] - vhi);
                }
            }
        }
        __syncthreads();

        float sacc[4][4];
#pragma unroll
        for (int ni = 0; ni < 4; ni++)
#pragma unroll
            for (int q = 0; q < 4; q++) sacc[ni][q] = 0.f;

#pragma unroll
        for (int ch = 0; ch < 16; ch++) {
            const int k0 = ch * 8;
            uint32_t ah[4], al[4];
            const int r0 = wm * 16;
            ah[0] = __float_as_uint(Qh[(r0 + g)     * AQP + k0 + t4]);
            ah[1] = __float_as_uint(Qh[(r0 + g + 8) * AQP + k0 + t4]);
            ah[2] = __float_as_uint(Qh[(r0 + g)     * AQP + k0 + t4 + 4]);
            ah[3] = __float_as_uint(Qh[(r0 + g + 8) * AQP + k0 + t4 + 4]);
            al[0] = __float_as_uint(Ql[(r0 + g)     * AQP + k0 + t4]);
            al[1] = __float_as_uint(Ql[(r0 + g + 8) * AQP + k0 + t4]);
            al[2] = __float_as_uint(Ql[(r0 + g)     * AQP + k0 + t4 + 4]);
            al[3] = __float_as_uint(Ql[(r0 + g + 8) * AQP + k0 + t4 + 4]);
#pragma unroll
            for (int ni = 0; ni < 4; ni++) {
                const int c8 = wn * 32 + ni * 8;
                uint32_t bh[2], bl[2];
                bh[0] = __float_as_uint(Kh[(c8 + g) * AQP + k0 + t4]);
                bh[1] = __float_as_uint(Kh[(c8 + g) * AQP + k0 + t4 + 4]);
                bl[0] = __float_as_uint(Kl[(c8 + g) * AQP + k0 + t4]);
                bl[1] = __float_as_uint(Kl[(c8 + g) * AQP + k0 + t4 + 4]);
                mma_tf32_16x8x8(sacc[ni], ah, bh);
                mma_tf32_16x8x8(sacc[ni], ah, bl);
                mma_tf32_16x8x8(sacc[ni], al, bh);
            }
        }

        const bool diag = (kt == qt);
#pragma unroll
        for (int ni = 0; ni < 4; ni++) {
            const int c0 = wn * 32 + ni * 8 + t4 * 2;
            const int rA = wm * 16 + g, rB = rA + 8;
            float s0 = sacc[ni][0] * scale, s1 = sacc[ni][1] * scale;
            float s2 = sacc[ni][2] * scale, s3 = sacc[ni][3] * scale;
            if (diag) {
                if (c0     > rA) s0 = -1e30f;
                if (c0 + 1 > rA) s1 = -1e30f;
                if (c0     > rB) s2 = -1e30f;
                if (c0 + 1 > rB) s3 = -1e30f;
            }
            Ps[rA * AVP + c0]     = s0;
            Ps[rA * AVP + c0 + 1] = s1;
            Ps[rB * AVP + c0]     = s2;
            Ps[rB * AVP + c0 + 1] = s3;
        }
        __syncthreads();

        {
            const int row = tid >> 2;
            const int q4  = tid & 3;
            float* pr = Ps + row * AVP + q4 * 16;
            float lmax = -1e30f;
#pragma unroll
            for (int j = 0; j < 16; j++) lmax = fmaxf(lmax, pr[j]);
            lmax = fmaxf(lmax, __shfl_xor_sync(0xffffffffu, lmax, 1));
            lmax = fmaxf(lmax, __shfl_xor_sync(0xffffffffu, lmax, 2));
            const float mold = Mr[row];
            const float mnew = fmaxf(mold, lmax);
            float lsum = 0.f;
#pragma unroll
            for (int j = 0; j < 16; j++) {
                float p = expf(pr[j] - mnew);
                pr[j] = p;
                lsum += p;
            }
            lsum += __shfl_xor_sync(0xffffffffu, lsum, 1);
            lsum += __shfl_xor_sync(0xffffffffu, lsum, 2);
            if (q4 == 0) {
                const float corr = expf(mold - mnew);
                Cr[row] = corr;
                Lr[row] = Lr[row] * corr + lsum;
                Mr[row] = mnew;
            }
        }
        __syncthreads();

        {
            const float cg  = Cr[wm * 16 + g];
            const float cg8 = Cr[wm * 16 + g + 8];
#pragma unroll
            for (int ni = 0; ni < 8; ni++) {
                acc_o[ni][0] *= cg;  acc_o[ni][1] *= cg;
                acc_o[ni][2] *= cg8; acc_o[ni][3] *= cg8;
            }
#pragma unroll
            for (int ch = 0; ch < 8; ch++) {
                const int k0 = ch * 8;
                const int r0 = wm * 16;
                float p0 = Ps[(r0 + g)     * AVP + k0 + t4];
                float p1 = Ps[(r0 + g + 8) * AVP + k0 + t4];
                float p2 = Ps[(r0 + g)     * AVP + k0 + t4 + 4];
                float p3 = Ps[(r0 + g + 8) * AVP + k0 + t4 + 4];
                uint32_t ah[4], al[4];
                float h0 = tf32_rna(p0), h1 = tf32_rna(p1);
                float h2 = tf32_rna(p2), h3 = tf32_rna(p3);
                ah[0] = __float_as_uint(h0); ah[1] = __float_as_uint(h1);
                ah[2] = __float_as_uint(h2); ah[3] = __float_as_uint(h3);
                al[0] = __float_as_uint(tf32_rna(p0 - h0));
                al[1] = __float_as_uint(tf32_rna(p1 - h1));
                al[2] = __float_as_uint(tf32_rna(p2 - h2));
                al[3] = __float_as_uint(tf32_rna(p3 - h3));
#pragma unroll
                for (int ni = 0; ni < 8; ni++) {
                    const int c8 = wn * 64 + ni * 8;
                    uint32_t bh[2], bl[2];
                    bh[0] = __float_as_uint(Vh[(c8 + g) * AVP + k0 + t4]);
                    bh[1] = __float_as_uint(Vh[(c8 + g) * AVP + k0 + t4 + 4]);
                    bl[0] = __float_as_uint(Vl[(c8 + g) * AVP + k0 + t4]);
                    bl[1] = __float_as_uint(Vl[(c8 + g) * AVP + k0 + t4 + 4]);
                    mma_tf32_16x8x8(acc_o[ni], ah, bh);
                    mma_tf32_16x8x8(acc_o[ni], ah, bl);
                    mma_tf32_16x8x8(acc_o[ni], al, bh);
                }
            }
        }
    }

    {
        const float invA = 1.f / Lr[wm * 16 + g];
        const float invB = 1.f / Lr[wm * 16 + g + 8];
        const int rowA = b * SDIM + qt * 64 + wm * 16 + g;
        const int rowB = rowA + 8;
#pragma unroll
        for (int ni = 0; ni < 8; ni++) {
            const int cc = h * DHDIM + wn * 64 + ni * 8 + t4 * 2;
            float2 lo = {tf32_rna(acc_o[ni][0] * invA), tf32_rna(acc_o[ni][1] * invA)};
            float2 hi = {tf32_rna(acc_o[ni][2] * invB), tf32_rna(acc_o[ni][3] * invB)};
            *(float2*)(O + (size_t)rowA * DDIM + cc) = lo;
            *(float2*)(O + (size_t)rowB * DDIM + cc) = hi;
        }
    }
}

// ---------------------------------------------------------------------------
extern "C" void kernel_launch(void* const* d_in, const int* in_sizes, int n_in,
                              void* d_out, int out_size)
{
    const float* x    = (const float*)d_in[0];
    const float* Wdq  = (const float*)d_in[1];
    const float* Wuq  = (const float*)d_in[2];
    const float* qg   = (const float*)d_in[3];
    const float* qb   = (const float*)d_in[4];
    const float* Wdkv = (const float*)d_in[5];
    const float* Wukv = (const float*)d_in[6];
    const float* kvg  = (const float*)d_in[7];
    const float* kvb  = (const float*)d_in[8];
    const float* Wo   = (const float*)d_in[9];
    float* out = (float*)d_out;

    float *c12, *Qb2, *KVb, *Ob, *xr, *Wt12, *Wt3, *Wt4, *Wor;
    cudaGetSymbolAddress((void**)&c12, g_c12);
    cudaGetSymbolAddress((void**)&Qb2, g_Q);
    cudaGetSymbolAddress((void**)&KVb, g_KV);
    cudaGetSymbolAddress((void**)&Ob,  g_O);
    cudaGetSymbolAddress((void**)&xr,  g_xr);
    cudaGetSymbolAddress((void**)&Wt12, g_Wt12);
    cudaGetSymbolAddress((void**)&Wt3, g_Wt3);
    cudaGetSymbolAddress((void**)&Wt4, g_Wt4);
    cudaGetSymbolAddress((void**)&Wor, g_Wor);

    cudaFuncSetAttribute(attn_mma_kernel, cudaFuncAttributeMaxDynamicSharedMemorySize,
                         ATTN_SMEM_BYTES);
    cudaFuncSetAttribute(tgemm_mma, cudaFuncAttributeMaxDynamicSharedMemorySize,
                         TG_SMEM);

    dim3 tb(32, 8);
    // Wt12 = [Wdq^T ; Wdkv^T]  (rows 0..2047 | 2048..4095, each row K-major)
    transpose_kernel<<<dim3(64,  64), tb>>>(Wdq,  Wt12, DDIM, DDIM);
    transpose_kernel<<<dim3(64,  64), tb>>>(Wdkv, Wt12 + (size_t)DDIM * DDIM,
                                            DDIM, DDIM);
    transpose_kernel<<<dim3(64,  64), tb>>>(Wuq,  Wt3, DDIM, DDIM);
    transpose_kernel<<<dim3(128, 64), tb>>>(Wukv, Wt4, DDIM, 2 * DDIM);
    round_kernel<<<(BS_ROWS * DDIM / 4 + 255) / 256, 256>>>(x,  xr,  BS_ROWS * DDIM / 4);
    round_kernel<<<(DDIM * DDIM / 4 + 255) / 256, 256>>>(Wo, Wor, DDIM * DDIM / 4);

    dim3 blk(256);

    // fused down-projection: [cq|ckv] = xr @ [Wdq|Wdkv]
    tgemm_mma<<<dim3(16, 32), blk, TG_SMEM>>>(xr, DDIM, Wt12, DDIM,
                                              c12, 2 * DDIM,
                                              BS_ROWS, 2 * DDIM, DDIM);

    float* ckv_out = (out_size >= 2 * BS_ROWS * DDIM)
                         ? (out + (size_t)BS_ROWS * DDIM) : nullptr;
    ln2_kernel<<<dim3(BS_ROWS, 2), 256>>>(c12, qg, qb, kvg, kvb, ckv_out);

    // up-projections (A = slices of c12, lda = 4096)
    tgemm_mma<<<dim3(8, 32),  blk, TG_SMEM>>>(c12,        2 * DDIM, Wt3, DDIM,
                                              Qb2, DDIM, BS_ROWS, DDIM, DDIM);
    tgemm_mma<<<dim3(16, 32), blk, TG_SMEM>>>(c12 + DDIM, 2 * DDIM, Wt4, DDIM,
                                              KVb, 2 * DDIM, BS_ROWS, 2 * DDIM, DDIM);

    rope_kernel<<<BS_ROWS, 1024>>>(Qb2, KVb);

    attn_mma_kernel<<<dim3(32, HDIM, BDIM), blk, ATTN_SMEM_BYTES>>>(Qb2, KVb, Ob);

    tgemm_mma<<<dim3(8, 32), blk, TG_SMEM>>>(Ob, DDIM, Wor, DDIM,
                                             out, DDIM, BS_ROWS, DDIM, DDIM);
}

// round 9
// speedup vs baseline: 3.1958x; 1.1509x over previous
#include <cuda_runtime.h>
#include <cuda_fp16.h>
#include <math.h>
#include <stdint.h>

// ---------------------------------------------------------------------------
// MLA prefill: B=2, S=2048, D=2048, H=16, dh=128
// Round 9: projection GEMMs switched to fp16 m16n8k16 (same 10-bit mantissa
// as tf32 -> same error, 2x mma rate). Attention stays split-tf32.
// ---------------------------------------------------------------------------

#define BDIM   2
#define SDIM   2048
#define DDIM   2048
#define HDIM   16
#define DHDIM  128
#define BS_ROWS 4096            // B*S

__device__ float  g_c12 [BS_ROWS * 2 * DDIM];   // GEMM1 out (float)
__device__ __half g_c12h[BS_ROWS * 2 * DDIM];   // LN'd, half (GEMM2/3 A)
__device__ float  g_Q   [BS_ROWS * DDIM];
__device__ float  g_KV  [BS_ROWS * 2 * DDIM];
__device__ __half g_Oh  [BS_ROWS * DDIM];       // attention out, half
__device__ __half g_xh  [BS_ROWS * DDIM];       // half x
__device__ __half g_Wt12[2 * DDIM * DDIM];      // [Wdq^T ; Wdkv^T] half
__device__ __half g_Wt3 [DDIM * DDIM];          // Wuq^T half
__device__ __half g_Wt4 [2 * DDIM * DDIM];      // Wukv^T half
__device__ __half g_Woh [DDIM * DDIM];          // Wo half (already [N,K])

__device__ __forceinline__ float tf32_rna(float x) {
    uint32_t u;
    asm("cvt.rna.tf32.f32 %0, %1;" : "=r"(u) : "f"(x));
    return __uint_as_float(u);
}

__device__ __forceinline__ void mma_tf32_16x8x8(float* d, const uint32_t* a,
                                                const uint32_t* b) {
    asm volatile(
        "mma.sync.aligned.m16n8k8.row.col.f32.tf32.tf32.f32 "
        "{%0,%1,%2,%3}, {%4,%5,%6,%7}, {%8,%9}, {%0,%1,%2,%3};\n"
        : "+f"(d[0]), "+f"(d[1]), "+f"(d[2]), "+f"(d[3])
        : "r"(a[0]), "r"(a[1]), "r"(a[2]), "r"(a[3]), "r"(b[0]), "r"(b[1]));
}

__device__ __forceinline__ void mma_f16_16x8x16(float* d, const uint32_t* a,
                                                const uint32_t* b) {
    asm volatile(
        "mma.sync.aligned.m16n8k16.row.col.f32.f16.f16.f32 "
        "{%0,%1,%2,%3}, {%4,%5,%6,%7}, {%8,%9}, {%0,%1,%2,%3};\n"
        : "+f"(d[0]), "+f"(d[1]), "+f"(d[2]), "+f"(d[3])
        : "r"(a[0]), "r"(a[1]), "r"(a[2]), "r"(a[3]), "r"(b[0]), "r"(b[1]));
}

__device__ __forceinline__ uint32_t smem_u32(const void* p) {
    uint32_t a;
    asm("{ .reg .u64 t; cvta.to.shared.u64 t, %1; cvt.u32.u64 %0, t; }"
        : "=r"(a) : "l"(p));
    return a;
}
__device__ __forceinline__ void cp16(uint32_t s, const void* g) {
    asm volatile("cp.async.cg.shared.global [%0], [%1], 16;" :: "r"(s), "l"(g));
}
__device__ __forceinline__ void cp_commit() {
    asm volatile("cp.async.commit_group;" ::: "memory");
}
template <int N>
__device__ __forceinline__ void cp_wait() {
    asm volatile("cp.async.wait_group %0;" :: "n"(N) : "memory");
}

// ---------------------------------------------------------------------------
// fp16 GEMM: C[M,N](f32) = A[M,K](f16) @ Bt[N,K](f16)^T.
// CTA tile 128(M) x 256(N), K chunk 32 halves, 3-stage cp.async ring,
// 8 warps as 2(M) x 4(N), each warp 64x64 via m16n8k16.
// smem pitch 40 halves -> conflict-free 32-bit fragment LDS.
// ---------------------------------------------------------------------------
#define HGP 40                               // halves per smem row
#define HG_AROWS 128
#define HG_BROWS 256
#define HG_BOFF (HG_AROWS * HGP)             // halves
#define HG_STG  ((HG_AROWS + HG_BROWS) * HGP)  // halves per stage
#define HG_SMEM (3 * HG_STG * 2)             // bytes

__global__ __launch_bounds__(256, 1) void hgemm_mma(
    const __half* __restrict__ A, int lda,
    const __half* __restrict__ Bt, int ldb,
    float* __restrict__ C, int ldc,
    int M, int N, int K)
{
    extern __shared__ __half hsm[];

    const int tid = threadIdx.x;
    const int wid = tid >> 5, lane = tid & 31;
    const int m0 = blockIdx.y * 128;
    const int n0 = blockIdx.x * 256;

    const int warp_m = wid & 1;
    const int warp_n = wid >> 1;
    const int g  = lane >> 2;
    const int t4 = lane & 3;

    float acc[4][8][4];
#pragma unroll
    for (int mi = 0; mi < 4; mi++)
#pragma unroll
        for (int ni = 0; ni < 8; ni++)
#pragma unroll
            for (int q = 0; q < 4; q++) acc[mi][ni][q] = 0.f;

    const int nch = K >> 5;                  // chunks of 32 halves

    // staging maps
    const int ar = tid >> 1;                 // 0..127 (A row)
    const int ac = tid & 1;                  // base 16B col (0/1), +2 second
    const __half* Ab = A + (size_t)(m0 + ar) * lda + ac * 8;
    const __half* Bb = Bt + (size_t)(n0 + tid) * ldb;   // B row = tid

    const uint32_t sbase = smem_u32(hsm);
    const uint32_t aoff  = (uint32_t)(ar * HGP + ac * 8) * 2;
    const uint32_t boff  = (uint32_t)(HG_BOFF + tid * HGP) * 2;

    // prologue: stage chunks 0 and 1
#pragma unroll
    for (int p = 0; p < 2; p++) {
        const uint32_t sb = sbase + p * (HG_STG * 2);
        const int k0g = p * 32;
#pragma unroll
        for (int j = 0; j < 2; j++)          // A: cols ac, ac+2
            cp16(sb + aoff + j * 32, Ab + k0g + j * 16);
#pragma unroll
        for (int c = 0; c < 4; c++)          // B: cols 0..3
            cp16(sb + boff + c * 16, Bb + k0g + c * 8);
        cp_commit();
    }

    for (int ch = 0; ch < nch; ch++) {
        cp_wait<1>();
        __syncthreads();

        if (ch + 2 < nch) {
            const uint32_t sb = sbase + ((ch + 2) % 3) * (HG_STG * 2);
            const int k0g = (ch + 2) * 32;
#pragma unroll
            for (int j = 0; j < 2; j++)
                cp16(sb + aoff + j * 32, Ab + k0g + j * 16);
#pragma unroll
            for (int c = 0; c < 4; c++)
                cp16(sb + boff + c * 16, Bb + k0g + c * 8);
        }
        cp_commit();

        const __half* As = hsm + (ch % 3) * HG_STG;
        const __half* Bs = As + HG_BOFF;
#pragma unroll
        for (int ks = 0; ks < 2; ks++) {
            const int k0 = ks * 16;
            uint32_t afr[4][4], bfr[8][2];
#pragma unroll
            for (int mi = 0; mi < 4; mi++) {
                const int r16 = warp_m * 64 + mi * 16;
                const int base = (r16 + g) * HGP + k0 + 2 * t4;
                afr[mi][0] = *(const uint32_t*)(As + base);
                afr[mi][1] = *(const uint32_t*)(As + base + 8 * HGP);
                afr[mi][2] = *(const uint32_t*)(As + base + 8);
                afr[mi][3] = *(const uint32_t*)(As + base + 8 * HGP + 8);
            }
#pragma unroll
            for (int ni = 0; ni < 8; ni++) {
                const int c8 = warp_n * 64 + ni * 8;
                const int bb = (c8 + g) * HGP + k0 + 2 * t4;
                bfr[ni][0] = *(const uint32_t*)(Bs + bb);
                bfr[ni][1] = *(const uint32_t*)(Bs + bb + 8);
            }
#pragma unroll
            for (int mi = 0; mi < 4; mi++)
#pragma unroll
                for (int ni = 0; ni < 8; ni++)
                    mma_f16_16x8x16(acc[mi][ni], afr[mi], bfr[ni]);
        }
    }

#pragma unroll
    for (int mi = 0; mi < 4; mi++) {
        const int r16 = m0 + warp_m * 64 + mi * 16;
#pragma unroll
        for (int ni = 0; ni < 8; ni++) {
            const int cc = n0 + warp_n * 64 + ni * 8 + t4 * 2;
            float2 lo = {acc[mi][ni][0], acc[mi][ni][1]};
            float2 hi = {acc[mi][ni][2], acc[mi][ni][3]};
            *(float2*)(C + (size_t)(r16 + g)     * ldc + cc) = lo;
            *(float2*)(C + (size_t)(r16 + g + 8) * ldc + cc) = hi;
        }
    }
}

// ---------------------------------------------------------------------------
// 32x32 tiled transpose -> half: Wt[C,R] = half(W[R,C]^T)
// ---------------------------------------------------------------------------
__global__ void transpose_kernel(const float* __restrict__ W, __half* __restrict__ Wt,
                                 int R, int C)
{
    __shared__ float t[32][33];
    const int c0 = blockIdx.x * 32, r0 = blockIdx.y * 32;
    const int x = threadIdx.x, y = threadIdx.y;
#pragma unroll
    for (int j = 0; j < 32; j += 8)
        t[y + j][x] = W[(size_t)(r0 + y + j) * C + c0 + x];
    __syncthreads();
#pragma unroll
    for (int j = 0; j < 32; j += 8)
        Wt[(size_t)(c0 + y + j) * R + r0 + x] = __float2half(t[x][y + j]);
}

// float -> half elementwise
__global__ void half_kernel(const float* __restrict__ in, __half* __restrict__ out,
                            int n4)
{
    const int i = blockIdx.x * blockDim.x + threadIdx.x;
    if (i < n4) {
        float4 v = ((const float4*)in)[i];
        __half2* o = (__half2*)out + i * 2;
        o[0] = __floats2half2_rn(v.x, v.y);
        o[1] = __floats2half2_rn(v.z, v.w);
    }
}

// ---------------------------------------------------------------------------
// Merged LayerNorm over both halves of C12 [row][cq|ckv] (float in).
// Writes half to C12h (GEMM input); part 1 mirrors full precision to out2.
// ---------------------------------------------------------------------------
__global__ void ln2_kernel(const float* __restrict__ C12, __half* __restrict__ C12h,
                           const float* __restrict__ g1, const float* __restrict__ b1,
                           const float* __restrict__ g2, const float* __restrict__ b2,
                           float* __restrict__ out2)
{
    const int row  = blockIdx.x;
    const int part = blockIdx.y;
    const int tid  = threadIdx.x;
    const float* xr = C12 + (size_t)row * (2 * DDIM) + part * DDIM;
    __half* xo = C12h + (size_t)row * (2 * DDIM) + part * DDIM;
    const float* gamma = part ? g2 : g1;
    const float* beta  = part ? b2 : b1;

    float v[8];
    float s = 0.f, sq = 0.f;
#pragma unroll
    for (int j = 0; j < 8; j++) {
        v[j] = xr[tid + j * 256];
        s  += v[j];
        sq += v[j] * v[j];
    }

    __shared__ float red[64];
#pragma unroll
    for (int off = 16; off; off >>= 1) {
        s  += __shfl_xor_sync(0xffffffffu, s,  off);
        sq += __shfl_xor_sync(0xffffffffu, sq, off);
    }
    const int wid = tid >> 5, lane = tid & 31;
    if (lane == 0) { red[wid] = s; red[32 + wid] = sq; }
    __syncthreads();
    if (wid == 0) {
        s  = (lane < 8) ? red[lane]      : 0.f;
        sq = (lane < 8) ? red[32 + lane] : 0.f;
#pragma unroll
        for (int off = 4; off; off >>= 1) {
            s  += __shfl_xor_sync(0xffffffffu, s,  off);
            sq += __shfl_xor_sync(0xffffffffu, sq, off);
        }
        if (lane == 0) { red[0] = s; red[1] = sq; }
    }
    __syncthreads();

    const float mean = red[0] * (1.f / DDIM);
    const float var  = red[1] * (1.f / DDIM) - mean * mean;
    const float rstd = rsqrtf(var + 1e-5f);

#pragma unroll
    for (int j = 0; j < 8; j++) {
        const int c = tid + j * 256;
        float y = (v[j] - mean) * rstd * gamma[c] + beta[c];
        if (part && out2) out2[(size_t)row * DDIM + c] = y;
        xo[c] = __float2half(y);
    }
}

// ---------------------------------------------------------------------------
__global__ void rope_kernel(float* __restrict__ Q, float* __restrict__ KV)
{
    const int row = blockIdx.x;
    const int t   = row & (SDIM - 1);
    const int tid = threadIdx.x;
    const int h   = tid >> 6;
    const int i   = tid & 63;

    const float freq = (float)exp(-(double)i * (log(10000.0) / 64.0));
    const float ang  = (float)t * freq;
    float sn, cs;
    sincosf(ang, &sn, &cs);

    const size_t qb = (size_t)row * DDIM + h * DHDIM + i;
    float x1 = Q[qb], x2 = Q[qb + 64];
    Q[qb]      = x1 * cs - x2 * sn;
    Q[qb + 64] = x2 * cs + x1 * sn;

    const size_t kb = (size_t)row * (2 * DDIM) + h * DHDIM + i;
    float y1 = KV[kb], y2 = KV[kb + 64];
    KV[kb]      = y1 * cs - y2 * sn;
    KV[kb + 64] = y2 * cs + y1 * sn;
}

// ---------------------------------------------------------------------------
// Flash attention with split-tf32 tensor cores. Epilogue writes half O.
// ---------------------------------------------------------------------------
#define AQP 132
#define AVP 68
#define OFF_QH 0
#define OFF_QL 8448
#define OFF_KH 16896
#define OFF_KL 25344
#define OFF_VH 33792
#define OFF_VL 42496
#define OFF_PS 51200
#define OFF_M  55552
#define OFF_L  55616
#define OFF_C  55680
#define ATTN_SMEM_FLOATS 55744
#define ATTN_SMEM_BYTES  (ATTN_SMEM_FLOATS * 4)

__global__ __launch_bounds__(256, 1) void attn_mma_kernel(
    const float* __restrict__ Q, const float* __restrict__ KV,
    __half* __restrict__ O)
{
    extern __shared__ float smx[];
    float* Qh = smx + OFF_QH;
    float* Ql = smx + OFF_QL;
    float* Kh = smx + OFF_KH;
    float* Kl = smx + OFF_KL;
    float* Vh = smx + OFF_VH;
    float* Vl = smx + OFF_VL;
    float* Ps = smx + OFF_PS;
    float* Mr = smx + OFF_M;
    float* Lr = smx + OFF_L;
    float* Cr = smx + OFF_C;

    const int qt = blockIdx.x, h = blockIdx.y, b = blockIdx.z;
    const int tid = threadIdx.x;
    const int wid = tid >> 5, lane = tid & 31;
    const int g = lane >> 2, t4 = lane & 3;
    const float scale = 0.088388347648318447f;

    const int wm = wid & 3;
    const int wn = wid >> 2;

    {
        const int r  = tid >> 2;
        const int c0 = tid & 3;
        const float* gq = Q + (size_t)(b * SDIM + qt * 64 + r) * DDIM + h * DHDIM;
#pragma unroll
        for (int rep = 0; rep < 8; rep++) {
            const int c4 = c0 + rep * 4;
            float4 v = *(const float4*)(gq + c4 * 4);
            float vv[4] = {v.x, v.y, v.z, v.w};
#pragma unroll
            for (int j = 0; j < 4; j++) {
                const int col = c4 * 4 + j;
                float hi = tf32_rna(vv[j]);
                Qh[r * AQP + col] = hi;
                Ql[r * AQP + col] = tf32_rna(vv[j] - hi);
            }
        }
        if (tid < 64) { Mr[tid] = -1e30f; Lr[tid] = 0.f; }
    }

    float acc_o[8][4];
#pragma unroll
    for (int ni = 0; ni < 8; ni++)
#pragma unroll
        for (int q = 0; q < 4; q++) acc_o[ni][q] = 0.f;

    for (int kt = 0; kt <= qt; kt++) {
        __syncthreads();

        {
            const int r  = tid >> 2;
            const int c0 = tid & 3;
            const float* gk = KV + (size_t)(b * SDIM + kt * 64 + r) * (2 * DDIM) + h * DHDIM;
            const float* gv = gk + DDIM;
#pragma unroll
            for (int rep = 0; rep < 8; rep++) {
                const int c4 = c0 + rep * 4;
                float4 kv4 = *(const float4*)(gk + c4 * 4);
                float4 vv4 = *(const float4*)(gv + c4 * 4);
                float kk[4] = {kv4.x, kv4.y, kv4.z, kv4.w};
                float vv[4] = {vv4.x, vv4.y, vv4.z, vv4.w};
#pragma unroll
                for (int j = 0; j < 4; j++) {
                    const int col = c4 * 4 + j;
                    float khi = tf32_rna(kk[j]);
                    Kh[r * AQP + col] = khi;
                    Kl[r * AQP + col] = tf32_rna(kk[j] - khi);
                    float vhi = tf32_rna(vv[j]);
                    Vh[col * AVP + r] = vhi;
                    Vl[col * AVP + r] = tf32_rna(vv[j] - vhi);
                }
            }
        }
        __syncthreads();

        float sacc[4][4];
#pragma unroll
        for (int ni = 0; ni < 4; ni++)
#pragma unroll
            for (int q = 0; q < 4; q++) sacc[ni][q] = 0.f;

#pragma unroll
        for (int ch = 0; ch < 16; ch++) {
            const int k0 = ch * 8;
            uint32_t ah[4], al[4];
            const int r0 = wm * 16;
            ah[0] = __float_as_uint(Qh[(r0 + g)     * AQP + k0 + t4]);
            ah[1] = __float_as_uint(Qh[(r0 + g + 8) * AQP + k0 + t4]);
            ah[2] = __float_as_uint(Qh[(r0 + g)     * AQP + k0 + t4 + 4]);
            ah[3] = __float_as_uint(Qh[(r0 + g + 8) * AQP + k0 + t4 + 4]);
            al[0] = __float_as_uint(Ql[(r0 + g)     * AQP + k0 + t4]);
            al[1] = __float_as_uint(Ql[(r0 + g + 8) * AQP + k0 + t4]);
            al[2] = __float_as_uint(Ql[(r0 + g)     * AQP + k0 + t4 + 4]);
            al[3] = __float_as_uint(Ql[(r0 + g + 8) * AQP + k0 + t4 + 4]);
#pragma unroll
            for (int ni = 0; ni < 4; ni++) {
                const int c8 = wn * 32 + ni * 8;
                uint32_t bh[2], bl[2];
                bh[0] = __float_as_uint(Kh[(c8 + g) * AQP + k0 + t4]);
                bh[1] = __float_as_uint(Kh[(c8 + g) * AQP + k0 + t4 + 4]);
                bl[0] = __float_as_uint(Kl[(c8 + g) * AQP + k0 + t4]);
                bl[1] = __float_as_uint(Kl[(c8 + g) * AQP + k0 + t4 + 4]);
                mma_tf32_16x8x8(sacc[ni], ah, bh);
                mma_tf32_16x8x8(sacc[ni], ah, bl);
                mma_tf32_16x8x8(sacc[ni], al, bh);
            }
        }

        const bool diag = (kt == qt);
#pragma unroll
        for (int ni = 0; ni < 4; ni++) {
            const int c0 = wn * 32 + ni * 8 + t4 * 2;
            const int rA = wm * 16 + g, rB = rA + 8;
            float s0 = sacc[ni][0] * scale, s1 = sacc[ni][1] * scale;
            float s2 = sacc[ni][2] * scale, s3 = sacc[ni][3] * scale;
            if (diag) {
                if (c0     > rA) s0 = -1e30f;
                if (c0 + 1 > rA) s1 = -1e30f;
                if (c0     > rB) s2 = -1e30f;
                if (c0 + 1 > rB) s3 = -1e30f;
            }
            Ps[rA * AVP + c0]     = s0;
            Ps[rA * AVP + c0 + 1] = s1;
            Ps[rB * AVP + c0]     = s2;
            Ps[rB * AVP + c0 + 1] = s3;
        }
        __syncthreads();

        {
            const int row = tid >> 2;
            const int q4  = tid & 3;
            float* pr = Ps + row * AVP + q4 * 16;
            float lmax = -1e30f;
#pragma unroll
            for (int j = 0; j < 16; j++) lmax = fmaxf(lmax, pr[j]);
            lmax = fmaxf(lmax, __shfl_xor_sync(0xffffffffu, lmax, 1));
            lmax = fmaxf(lmax, __shfl_xor_sync(0xffffffffu, lmax, 2));
            const float mold = Mr[row];
            const float mnew = fmaxf(mold, lmax);
            float lsum = 0.f;
#pragma unroll
            for (int j = 0; j < 16; j++) {
                float p = expf(pr[j] - mnew);
                pr[j] = p;
                lsum += p;
            }
            lsum += __shfl_xor_sync(0xffffffffu, lsum, 1);
            lsum += __shfl_xor_sync(0xffffffffu, lsum, 2);
            if (q4 == 0) {
                const float corr = expf(mold - mnew);
                Cr[row] = corr;
                Lr[row] = Lr[row] * corr + lsum;
                Mr[row] = mnew;
            }
        }
        __syncthreads();

        {
            const float cg  = Cr[wm * 16 + g];
            const float cg8 = Cr[wm * 16 + g + 8];
#pragma unroll
            for (int ni = 0; ni < 8; ni++) {
                acc_o[ni][0] *= cg;  acc_o[ni][1] *= cg;
                acc_o[ni][2] *= cg8; acc_o[ni][3] *= cg8;
            }
#pragma unroll
            for (int ch = 0; ch < 8; ch++) {
                const int k0 = ch * 8;
                const int r0 = wm * 16;
                float p0 = Ps[(r0 + g)     * AVP + k0 + t4];
                float p1 = Ps[(r0 + g + 8) * AVP + k0 + t4];
                float p2 = Ps[(r0 + g)     * AVP + k0 + t4 + 4];
                float p3 = Ps[(r0 + g + 8) * AVP + k0 + t4 + 4];
                uint32_t ah[4], al[4];
                float h0 = tf32_rna(p0), h1 = tf32_rna(p1);
                float h2 = tf32_rna(p2), h3 = tf32_rna(p3);
                ah[0] = __float_as_uint(h0); ah[1] = __float_as_uint(h1);
                ah[2] = __float_as_uint(h2); ah[3] = __float_as_uint(h3);
                al[0] = __float_as_uint(tf32_rna(p0 - h0));
                al[1] = __float_as_uint(tf32_rna(p1 - h1));
                al[2] = __float_as_uint(tf32_rna(p2 - h2));
                al[3] = __float_as_uint(tf32_rna(p3 - h3));
#pragma unroll
                for (int ni = 0; ni < 8; ni++) {
                    const int c8 = wn * 64 + ni * 8;
                    uint32_t bh[2], bl[2];
                    bh[0] = __float_as_uint(Vh[(c8 + g) * AVP + k0 + t4]);
                    bh[1] = __float_as_uint(Vh[(c8 + g) * AVP + k0 + t4 + 4]);
                    bl[0] = __float_as_uint(Vl[(c8 + g) * AVP + k0 + t4]);
                    bl[1] = __float_as_uint(Vl[(c8 + g) * AVP + k0 + t4 + 4]);
                    mma_tf32_16x8x8(acc_o[ni], ah, bh);
                    mma_tf32_16x8x8(acc_o[ni], ah, bl);
                    mma_tf32_16x8x8(acc_o[ni], al, bh);
                }
            }
        }
    }

    // epilogue: normalize, write half O (feeds final fp16 GEMM)
    {
        const float invA = 1.f / Lr[wm * 16 + g];
        const float invB = 1.f / Lr[wm * 16 + g + 8];
        const int rowA = b * SDIM + qt * 64 + wm * 16 + g;
        const int rowB = rowA + 8;
#pragma unroll
        for (int ni = 0; ni < 8; ni++) {
            const int cc = h * DHDIM + wn * 64 + ni * 8 + t4 * 2;
            __half2 lo = __floats2half2_rn(acc_o[ni][0] * invA, acc_o[ni][1] * invA);
            __half2 hi = __floats2half2_rn(acc_o[ni][2] * invB, acc_o[ni][3] * invB);
            *(__half2*)(O + (size_t)rowA * DDIM + cc) = lo;
            *(__half2*)(O + (size_t)rowB * DDIM + cc) = hi;
        }
    }
}

// ---------------------------------------------------------------------------
extern "C" void kernel_launch(void* const* d_in, const int* in_sizes, int n_in,
                              void* d_out, int out_size)
{
    const float* x    = (const float*)d_in[0];
    const float* Wdq  = (const float*)d_in[1];
    const float* Wuq  = (const float*)d_in[2];
    const float* qg   = (const float*)d_in[3];
    const float* qb   = (const float*)d_in[4];
    const float* Wdkv = (const float*)d_in[5];
    const float* Wukv = (const float*)d_in[6];
    const float* kvg  = (const float*)d_in[7];
    const float* kvb  = (const float*)d_in[8];
    const float* Wo   = (const float*)d_in[9];
    float* out = (float*)d_out;

    float *c12, *Qb2, *KVb;
    __half *c12h, *Oh, *xh, *Wt12, *Wt3, *Wt4, *Woh;
    cudaGetSymbolAddress((void**)&c12,  g_c12);
    cudaGetSymbolAddress((void**)&c12h, g_c12h);
    cudaGetSymbolAddress((void**)&Qb2,  g_Q);
    cudaGetSymbolAddress((void**)&KVb,  g_KV);
    cudaGetSymbolAddress((void**)&Oh,   g_Oh);
    cudaGetSymbolAddress((void**)&xh,   g_xh);
    cudaGetSymbolAddress((void**)&Wt12, g_Wt12);
    cudaGetSymbolAddress((void**)&Wt3,  g_Wt3);
    cudaGetSymbolAddress((void**)&Wt4,  g_Wt4);
    cudaGetSymbolAddress((void**)&Woh,  g_Woh);

    cudaFuncSetAttribute(attn_mma_kernel, cudaFuncAttributeMaxDynamicSharedMemorySize,
                         ATTN_SMEM_BYTES);
    cudaFuncSetAttribute(hgemm_mma, cudaFuncAttributeMaxDynamicSharedMemorySize,
                         HG_SMEM);

    dim3 tb(32, 8);
    // Wt12 = [Wdq^T ; Wdkv^T]  (half, K-major rows)
    transpose_kernel<<<dim3(64,  64), tb>>>(Wdq,  Wt12, DDIM, DDIM);
    transpose_kernel<<<dim3(64,  64), tb>>>(Wdkv, Wt12 + (size_t)DDIM * DDIM,
                                            DDIM, DDIM);
    transpose_kernel<<<dim3(64,  64), tb>>>(Wuq,  Wt3, DDIM, DDIM);
    transpose_kernel<<<dim3(128, 64), tb>>>(Wukv, Wt4, DDIM, 2 * DDIM);
    half_kernel<<<(BS_ROWS * DDIM / 4 + 255) / 256, 256>>>(x,  xh, BS_ROWS * DDIM / 4);
    half_kernel<<<(DDIM * DDIM / 4 + 255) / 256, 256>>>(Wo, Woh, DDIM * DDIM / 4);

    dim3 blk(256);

    // fused down-projection: [cq|ckv] = x @ [Wdq|Wdkv]
    hgemm_mma<<<dim3(16, 32), blk, HG_SMEM>>>(xh, DDIM, Wt12, DDIM,
                                              c12, 2 * DDIM,
                                              BS_ROWS, 2 * DDIM, DDIM);

    float* ckv_out = (out_size >= 2 * BS_ROWS * DDIM)
                         ? (out + (size_t)BS_ROWS * DDIM) : nullptr;
    ln2_kernel<<<dim3(BS_ROWS, 2), 256>>>(c12, c12h, qg, qb, kvg, kvb, ckv_out);

    // up-projections (A = half slices of c12h, lda = 4096)
    hgemm_mma<<<dim3(8, 32),  blk, HG_SMEM>>>(c12h,        2 * DDIM, Wt3, DDIM,
                                              Qb2, DDIM, BS_ROWS, DDIM, DDIM);
    hgemm_mma<<<dim3(16, 32), blk, HG_SMEM>>>(c12h + DDIM, 2 * DDIM, Wt4, DDIM,
                                              KVb, 2 * DDIM, BS_ROWS, 2 * DDIM, DDIM);

    rope_kernel<<<BS_ROWS, 1024>>>(Qb2, KVb);

    attn_mma_kernel<<<dim3(32, HDIM, BDIM), blk, ATTN_SMEM_BYTES>>>(Qb2, KVb, Oh);

    // out = O @ Wo^T
    hgemm_mma<<<dim3(8, 32), blk, HG_SMEM>>>(Oh, DDIM, Woh, DDIM,
                                             out, DDIM, BS_ROWS, DDIM, DDIM);
}

// round 10
// speedup vs baseline: 3.8401x; 1.2016x over previous
#include <cuda_runtime.h>
#include <cuda_fp16.h>
#include <math.h>
#include <stdint.h>

// ---------------------------------------------------------------------------
// MLA prefill: B=2, S=2048, D=2048, H=16, dh=128
// Round 10: attention moved from split-tf32 (3x k8) to split-fp16 (3x k16)
// -> attention mma work halves at ~fp32 accuracy. Causal tiles launched
// longest-first. fp16 GEMMs unchanged from R9.
// ---------------------------------------------------------------------------

#define BDIM   2
#define SDIM   2048
#define DDIM   2048
#define HDIM   16
#define DHDIM  128
#define BS_ROWS 4096            // B*S

__device__ float  g_c12 [BS_ROWS * 2 * DDIM];
__device__ __half g_c12h[BS_ROWS * 2 * DDIM];
__device__ float  g_Q   [BS_ROWS * DDIM];
__device__ float  g_KV  [BS_ROWS * 2 * DDIM];
__device__ __half g_Oh  [BS_ROWS * DDIM];
__device__ __half g_xh  [BS_ROWS * DDIM];
__device__ __half g_Wt12[2 * DDIM * DDIM];
__device__ __half g_Wt3 [DDIM * DDIM];
__device__ __half g_Wt4 [2 * DDIM * DDIM];
__device__ __half g_Woh [DDIM * DDIM];

__device__ __forceinline__ void mma_f16_16x8x16(float* d, const uint32_t* a,
                                                const uint32_t* b) {
    asm volatile(
        "mma.sync.aligned.m16n8k16.row.col.f32.f16.f16.f32 "
        "{%0,%1,%2,%3}, {%4,%5,%6,%7}, {%8,%9}, {%0,%1,%2,%3};\n"
        : "+f"(d[0]), "+f"(d[1]), "+f"(d[2]), "+f"(d[3])
        : "r"(a[0]), "r"(a[1]), "r"(a[2]), "r"(a[3]), "r"(b[0]), "r"(b[1]));
}

__device__ __forceinline__ uint32_t smem_u32(const void* p) {
    uint32_t a;
    asm("{ .reg .u64 t; cvta.to.shared.u64 t, %1; cvt.u32.u64 %0, t; }"
        : "=r"(a) : "l"(p));
    return a;
}
__device__ __forceinline__ void cp16(uint32_t s, const void* g) {
    asm volatile("cp.async.cg.shared.global [%0], [%1], 16;" :: "r"(s), "l"(g));
}
__device__ __forceinline__ void cp_commit() {
    asm volatile("cp.async.commit_group;" ::: "memory");
}
template <int N>
__device__ __forceinline__ void cp_wait() {
    asm volatile("cp.async.wait_group %0;" :: "n"(N) : "memory");
}

// ---------------------------------------------------------------------------
// fp16 GEMM (unchanged from R9): C[M,N](f32) = A[M,K](f16) @ Bt[N,K](f16)^T.
// ---------------------------------------------------------------------------
#define HGP 40
#define HG_AROWS 128
#define HG_BROWS 256
#define HG_BOFF (HG_AROWS * HGP)
#define HG_STG  ((HG_AROWS + HG_BROWS) * HGP)
#define HG_SMEM (3 * HG_STG * 2)

__global__ __launch_bounds__(256, 1) void hgemm_mma(
    const __half* __restrict__ A, int lda,
    const __half* __restrict__ Bt, int ldb,
    float* __restrict__ C, int ldc,
    int M, int N, int K)
{
    extern __shared__ __half hsm[];

    const int tid = threadIdx.x;
    const int wid = tid >> 5, lane = tid & 31;
    const int m0 = blockIdx.y * 128;
    const int n0 = blockIdx.x * 256;

    const int warp_m = wid & 1;
    const int warp_n = wid >> 1;
    const int g  = lane >> 2;
    const int t4 = lane & 3;

    float acc[4][8][4];
#pragma unroll
    for (int mi = 0; mi < 4; mi++)
#pragma unroll
        for (int ni = 0; ni < 8; ni++)
#pragma unroll
            for (int q = 0; q < 4; q++) acc[mi][ni][q] = 0.f;

    const int nch = K >> 5;

    const int ar = tid >> 1;
    const int ac = tid & 1;
    const __half* Ab = A + (size_t)(m0 + ar) * lda + ac * 8;
    const __half* Bb = Bt + (size_t)(n0 + tid) * ldb;

    const uint32_t sbase = smem_u32(hsm);
    const uint32_t aoff  = (uint32_t)(ar * HGP + ac * 8) * 2;
    const uint32_t boff  = (uint32_t)(HG_BOFF + tid * HGP) * 2;

#pragma unroll
    for (int p = 0; p < 2; p++) {
        const uint32_t sb = sbase + p * (HG_STG * 2);
        const int k0g = p * 32;
#pragma unroll
        for (int j = 0; j < 2; j++)
            cp16(sb + aoff + j * 32, Ab + k0g + j * 16);
#pragma unroll
        for (int c = 0; c < 4; c++)
            cp16(sb + boff + c * 16, Bb + k0g + c * 8);
        cp_commit();
    }

    for (int ch = 0; ch < nch; ch++) {
        cp_wait<1>();
        __syncthreads();

        if (ch + 2 < nch) {
            const uint32_t sb = sbase + ((ch + 2) % 3) * (HG_STG * 2);
            const int k0g = (ch + 2) * 32;
#pragma unroll
            for (int j = 0; j < 2; j++)
                cp16(sb + aoff + j * 32, Ab + k0g + j * 16);
#pragma unroll
            for (int c = 0; c < 4; c++)
                cp16(sb + boff + c * 16, Bb + k0g + c * 8);
        }
        cp_commit();

        const __half* As = hsm + (ch % 3) * HG_STG;
        const __half* Bs = As + HG_BOFF;
#pragma unroll
        for (int ks = 0; ks < 2; ks++) {
            const int k0 = ks * 16;
            uint32_t afr[4][4], bfr[8][2];
#pragma unroll
            for (int mi = 0; mi < 4; mi++) {
                const int r16 = warp_m * 64 + mi * 16;
                const int base = (r16 + g) * HGP + k0 + 2 * t4;
                afr[mi][0] = *(const uint32_t*)(As + base);
                afr[mi][1] = *(const uint32_t*)(As + base + 8 * HGP);
                afr[mi][2] = *(const uint32_t*)(As + base + 8);
                afr[mi][3] = *(const uint32_t*)(As + base + 8 * HGP + 8);
            }
#pragma unroll
            for (int ni = 0; ni < 8; ni++) {
                const int c8 = warp_n * 64 + ni * 8;
                const int bb = (c8 + g) * HGP + k0 + 2 * t4;
                bfr[ni][0] = *(const uint32_t*)(Bs + bb);
                bfr[ni][1] = *(const uint32_t*)(Bs + bb + 8);
            }
#pragma unroll
            for (int mi = 0; mi < 4; mi++)
#pragma unroll
                for (int ni = 0; ni < 8; ni++)
                    mma_f16_16x8x16(acc[mi][ni], afr[mi], bfr[ni]);
        }
    }

#pragma unroll
    for (int mi = 0; mi < 4; mi++) {
        const int r16 = m0 + warp_m * 64 + mi * 16;
#pragma unroll
        for (int ni = 0; ni < 8; ni++) {
            const int cc = n0 + warp_n * 64 + ni * 8 + t4 * 2;
            float2 lo = {acc[mi][ni][0], acc[mi][ni][1]};
            float2 hi = {acc[mi][ni][2], acc[mi][ni][3]};
            *(float2*)(C + (size_t)(r16 + g)     * ldc + cc) = lo;
            *(float2*)(C + (size_t)(r16 + g + 8) * ldc + cc) = hi;
        }
    }
}

// ---------------------------------------------------------------------------
__global__ void transpose_kernel(const float* __restrict__ W, __half* __restrict__ Wt,
                                 int R, int C)
{
    __shared__ float t[32][33];
    const int c0 = blockIdx.x * 32, r0 = blockIdx.y * 32;
    const int x = threadIdx.x, y = threadIdx.y;
#pragma unroll
    for (int j = 0; j < 32; j += 8)
        t[y + j][x] = W[(size_t)(r0 + y + j) * C + c0 + x];
    __syncthreads();
#pragma unroll
    for (int j = 0; j < 32; j += 8)
        Wt[(size_t)(c0 + y + j) * R + r0 + x] = __float2half(t[x][y + j]);
}

__global__ void half_kernel(const float* __restrict__ in, __half* __restrict__ out,
                            int n4)
{
    const int i = blockIdx.x * blockDim.x + threadIdx.x;
    if (i < n4) {
        float4 v = ((const float4*)in)[i];
        __half2* o = (__half2*)out + i * 2;
        o[0] = __floats2half2_rn(v.x, v.y);
        o[1] = __floats2half2_rn(v.z, v.w);
    }
}

// ---------------------------------------------------------------------------
__global__ void ln2_kernel(const float* __restrict__ C12, __half* __restrict__ C12h,
                           const float* __restrict__ g1, const float* __restrict__ b1,
                           const float* __restrict__ g2, const float* __restrict__ b2,
                           float* __restrict__ out2)
{
    const int row  = blockIdx.x;
    const int part = blockIdx.y;
    const int tid  = threadIdx.x;
    const float* xr = C12 + (size_t)row * (2 * DDIM) + part * DDIM;
    __half* xo = C12h + (size_t)row * (2 * DDIM) + part * DDIM;
    const float* gamma = part ? g2 : g1;
    const float* beta  = part ? b2 : b1;

    float v[8];
    float s = 0.f, sq = 0.f;
#pragma unroll
    for (int j = 0; j < 8; j++) {
        v[j] = xr[tid + j * 256];
        s  += v[j];
        sq += v[j] * v[j];
    }

    __shared__ float red[64];
#pragma unroll
    for (int off = 16; off; off >>= 1) {
        s  += __shfl_xor_sync(0xffffffffu, s,  off);
        sq += __shfl_xor_sync(0xffffffffu, sq, off);
    }
    const int wid = tid >> 5, lane = tid & 31;
    if (lane == 0) { red[wid] = s; red[32 + wid] = sq; }
    __syncthreads();
    if (wid == 0) {
        s  = (lane < 8) ? red[lane]      : 0.f;
        sq = (lane < 8) ? red[32 + lane] : 0.f;
#pragma unroll
        for (int off = 4; off; off >>= 1) {
            s  += __shfl_xor_sync(0xffffffffu, s,  off);
            sq += __shfl_xor_sync(0xffffffffu, sq, off);
        }
        if (lane == 0) { red[0] = s; red[1] = sq; }
    }
    __syncthreads();

    const float mean = red[0] * (1.f / DDIM);
    const float var  = red[1] * (1.f / DDIM) - mean * mean;
    const float rstd = rsqrtf(var + 1e-5f);

#pragma unroll
    for (int j = 0; j < 8; j++) {
        const int c = tid + j * 256;
        float y = (v[j] - mean) * rstd * gamma[c] + beta[c];
        if (part && out2) out2[(size_t)row * DDIM + c] = y;
        xo[c] = __float2half(y);
    }
}

// ---------------------------------------------------------------------------
__global__ void rope_kernel(float* __restrict__ Q, float* __restrict__ KV)
{
    const int row = blockIdx.x;
    const int t   = row & (SDIM - 1);
    const int tid = threadIdx.x;
    const int h   = tid >> 6;
    const int i   = tid & 63;

    const float freq = (float)exp(-(double)i * (log(10000.0) / 64.0));
    const float ang  = (float)t * freq;
    float sn, cs;
    sincosf(ang, &sn, &cs);

    const size_t qb = (size_t)row * DDIM + h * DHDIM + i;
    float x1 = Q[qb], x2 = Q[qb + 64];
    Q[qb]      = x1 * cs - x2 * sn;
    Q[qb + 64] = x2 * cs + x1 * sn;

    const size_t kb = (size_t)row * (2 * DDIM) + h * DHDIM + i;
    float y1 = KV[kb], y2 = KV[kb + 64];
    KV[kb]      = y1 * cs - y2 * sn;
    KV[kb + 64] = y2 * cs + y1 * sn;
}

// ---------------------------------------------------------------------------
// Flash attention with split-fp16 tensor cores (3-term Markidis, f32 accum).
// Q/K hi/lo halves [64][136]; V^T hi/lo halves [128][72]; P f32 [64][68],
// split to fp16 on the fly. qt = 31 - blockIdx.x (longest tiles first).
// ---------------------------------------------------------------------------
#define AQPH 136                 // Q/K pitch (halves)
#define AVPH 72                  // V^T pitch (halves)
#define AVP  68                  // Ps pitch (floats)
#define QH_OFF 0
#define QL_OFF 17408
#define KH_OFF 34816
#define KL_OFF 52224
#define VH_OFF 69632
#define VL_OFF 88064
#define PS_OFF 106496
#define M_OFF  123904
#define L_OFF  124160
#define C_OFF  124416
#define ATTN_SMEM_BYTES 124672

__global__ __launch_bounds__(256, 1) void attn_mma_kernel(
    const float* __restrict__ Q, const float* __restrict__ KV,
    __half* __restrict__ O)
{
    extern __shared__ char smc[];
    __half* Qh = (__half*)(smc + QH_OFF);
    __half* Ql = (__half*)(smc + QL_OFF);
    __half* Kh = (__half*)(smc + KH_OFF);
    __half* Kl = (__half*)(smc + KL_OFF);
    __half* Vh = (__half*)(smc + VH_OFF);
    __half* Vl = (__half*)(smc + VL_OFF);
    float*  Ps = (float*)(smc + PS_OFF);
    float*  Mr = (float*)(smc + M_OFF);
    float*  Lr = (float*)(smc + L_OFF);
    float*  Cr = (float*)(smc + C_OFF);

    const int qt = 31 - blockIdx.x;          // longest-first scheduling
    const int h = blockIdx.y, b = blockIdx.z;
    const int tid = threadIdx.x;
    const int wid = tid >> 5, lane = tid & 31;
    const int g = lane >> 2, t4 = lane & 3;
    const float scale = 0.088388347648318447f;   // 1/sqrt(128)

    const int wm = wid & 3;
    const int wn = wid >> 2;

    // ---- stage Q (hi/lo halves) + init m/l ----
    {
        const int r  = tid >> 2;
        const int c0 = tid & 3;
        const float* gq = Q + (size_t)(b * SDIM + qt * 64 + r) * DDIM + h * DHDIM;
#pragma unroll
        for (int rep = 0; rep < 8; rep++) {
            const int c4 = c0 + rep * 4;
            float4 v = *(const float4*)(gq + c4 * 4);
            float vv[4] = {v.x, v.y, v.z, v.w};
#pragma unroll
            for (int j = 0; j < 4; j++) {
                const int col = c4 * 4 + j;
                __half hi = __float2half(vv[j]);
                Qh[r * AQPH + col] = hi;
                Ql[r * AQPH + col] = __float2half(vv[j] - __half2float(hi));
            }
        }
        if (tid < 64) { Mr[tid] = -1e30f; Lr[tid] = 0.f; }
    }

    float acc_o[8][4];
#pragma unroll
    for (int ni = 0; ni < 8; ni++)
#pragma unroll
        for (int q = 0; q < 4; q++) acc_o[ni][q] = 0.f;

    for (int kt = 0; kt <= qt; kt++) {
        __syncthreads();

        // ---- stage K (hi/lo, [key][dh]) and V (hi/lo, transposed [dh][key]) ----
        {
            const int r  = tid >> 2;
            const int c0 = tid & 3;
            const float* gk = KV + (size_t)(b * SDIM + kt * 64 + r) * (2 * DDIM) + h * DHDIM;
            const float* gv = gk + DDIM;
#pragma unroll
            for (int rep = 0; rep < 8; rep++) {
                const int c4 = c0 + rep * 4;
                float4 kv4 = *(const float4*)(gk + c4 * 4);
                float4 vv4 = *(const float4*)(gv + c4 * 4);
                float kk[4] = {kv4.x, kv4.y, kv4.z, kv4.w};
                float vv[4] = {vv4.x, vv4.y, vv4.z, vv4.w};
#pragma unroll
                for (int j = 0; j < 4; j++) {
                    const int col = c4 * 4 + j;
                    __half khi = __float2half(kk[j]);
                    Kh[r * AQPH + col] = khi;
                    Kl[r * AQPH + col] = __float2half(kk[j] - __half2float(khi));
                    __half vhi = __float2half(vv[j]);
                    Vh[col * AVPH + r] = vhi;
                    Vl[col * AVPH + r] = __float2half(vv[j] - __half2float(vhi));
                }
            }
        }
        __syncthreads();

        // ---- QK^T: S[16x32] per warp, split-fp16, 8 chunks of k16 ----
        float sacc[4][4];
#pragma unroll
        for (int ni = 0; ni < 4; ni++)
#pragma unroll
            for (int q = 0; q < 4; q++) sacc[ni][q] = 0.f;

#pragma unroll
        for (int ch = 0; ch < 8; ch++) {
            const int k0 = ch * 16;
            const int r0 = wm * 16;
            uint32_t ah[4], al[4];
            const int ab = (r0 + g) * AQPH + k0 + 2 * t4;
            ah[0] = *(const uint32_t*)(Qh + ab);
            ah[1] = *(const uint32_t*)(Qh + ab + 8 * AQPH);
            ah[2] = *(const uint32_t*)(Qh + ab + 8);
            ah[3] = *(const uint32_t*)(Qh + ab + 8 * AQPH + 8);
            al[0] = *(const uint32_t*)(Ql + ab);
            al[1] = *(const uint32_t*)(Ql + ab + 8 * AQPH);
            al[2] = *(const uint32_t*)(Ql + ab + 8);
            al[3] = *(const uint32_t*)(Ql + ab + 8 * AQPH + 8);
#pragma unroll
            for (int ni = 0; ni < 4; ni++) {
                const int c8 = wn * 32 + ni * 8;
                const int bb = (c8 + g) * AQPH + k0 + 2 * t4;
                uint32_t bh[2], bl[2];
                bh[0] = *(const uint32_t*)(Kh + bb);
                bh[1] = *(const uint32_t*)(Kh + bb + 8);
                bl[0] = *(const uint32_t*)(Kl + bb);
                bl[1] = *(const uint32_t*)(Kl + bb + 8);
                mma_f16_16x8x16(sacc[ni], ah, bh);
                mma_f16_16x8x16(sacc[ni], ah, bl);
                mma_f16_16x8x16(sacc[ni], al, bh);
            }
        }

        // ---- scale + causal mask -> Ps (f32) ----
        const bool diag = (kt == qt);
#pragma unroll
        for (int ni = 0; ni < 4; ni++) {
            const int c0 = wn * 32 + ni * 8 + t4 * 2;
            const int rA = wm * 16 + g, rB = rA + 8;
            float s0 = sacc[ni][0] * scale, s1 = sacc[ni][1] * scale;
            float s2 = sacc[ni][2] * scale, s3 = sacc[ni][3] * scale;
            if (diag) {
                if (c0     > rA) s0 = -1e30f;
                if (c0 + 1 > rA) s1 = -1e30f;
                if (c0     > rB) s2 = -1e30f;
                if (c0 + 1 > rB) s3 = -1e30f;
            }
            Ps[rA * AVP + c0]     = s0;
            Ps[rA * AVP + c0 + 1] = s1;
            Ps[rB * AVP + c0]     = s2;
            Ps[rB * AVP + c0 + 1] = s3;
        }
        __syncthreads();

        // ---- online softmax (4 threads per row) ----
        {
            const int row = tid >> 2;
            const int q4  = tid & 3;
            float* pr = Ps + row * AVP + q4 * 16;
            float lmax = -1e30f;
#pragma unroll
            for (int j = 0; j < 16; j++) lmax = fmaxf(lmax, pr[j]);
            lmax = fmaxf(lmax, __shfl_xor_sync(0xffffffffu, lmax, 1));
            lmax = fmaxf(lmax, __shfl_xor_sync(0xffffffffu, lmax, 2));
            const float mold = Mr[row];
            const float mnew = fmaxf(mold, lmax);
            float lsum = 0.f;
#pragma unroll
            for (int j = 0; j < 16; j++) {
                float p = expf(pr[j] - mnew);
                pr[j] = p;
                lsum += p;
            }
            lsum += __shfl_xor_sync(0xffffffffu, lsum, 1);
            lsum += __shfl_xor_sync(0xffffffffu, lsum, 2);
            if (q4 == 0) {
                const float corr = expf(mold - mnew);
                Cr[row] = corr;
                Lr[row] = Lr[row] * corr + lsum;
                Mr[row] = mnew;
            }
        }
        __syncthreads();

        // ---- PV: O[16x64] per warp, split-fp16, 4 chunks of k16 ----
        {
            const float cg  = Cr[wm * 16 + g];
            const float cg8 = Cr[wm * 16 + g + 8];
#pragma unroll
            for (int ni = 0; ni < 8; ni++) {
                acc_o[ni][0] *= cg;  acc_o[ni][1] *= cg;
                acc_o[ni][2] *= cg8; acc_o[ni][3] *= cg8;
            }
#pragma unroll
            for (int ch = 0; ch < 4; ch++) {
                const int k0 = ch * 16;
                const int r0 = wm * 16;
                // P fragments: 4 float2 -> hi/lo half2 pairs
                uint32_t ah[4], al[4];
#pragma unroll
                for (int fi = 0; fi < 4; fi++) {
                    const int rr = r0 + g + (fi & 1) * 8;
                    const int kk = k0 + ((fi >> 1) ? 8 : 0) + 2 * t4;
                    float2 p2 = *(const float2*)(Ps + rr * AVP + kk);
                    __half2 hi2 = __floats2half2_rn(p2.x, p2.y);
                    float2 lo2f = {p2.x - __low2float(hi2), p2.y - __high2float(hi2)};
                    __half2 lo2 = __floats2half2_rn(lo2f.x, lo2f.y);
                    ah[fi] = *(const uint32_t*)&hi2;
                    al[fi] = *(const uint32_t*)&lo2;
                }
#pragma unroll
                for (int ni = 0; ni < 8; ni++) {
                    const int c8 = wn * 64 + ni * 8;
                    const int bb = (c8 + g) * AVPH + k0 + 2 * t4;
                    uint32_t bh[2], bl[2];
                    bh[0] = *(const uint32_t*)(Vh + bb);
                    bh[1] = *(const uint32_t*)(Vh + bb + 8);
                    bl[0] = *(const uint32_t*)(Vl + bb);
                    bl[1] = *(const uint32_t*)(Vl + bb + 8);
                    mma_f16_16x8x16(acc_o[ni], ah, bh);
                    mma_f16_16x8x16(acc_o[ni], ah, bl);
                    mma_f16_16x8x16(acc_o[ni], al, bh);
                }
            }
        }
    }

    // ---- epilogue: normalize, write half O ----
    {
        const float invA = 1.f / Lr[wm * 16 + g];
        const float invB = 1.f / Lr[wm * 16 + g + 8];
        const int rowA = b * SDIM + qt * 64 + wm * 16 + g;
        const int rowB = rowA + 8;
#pragma unroll
        for (int ni = 0; ni < 8; ni++) {
            const int cc = h * DHDIM + wn * 64 + ni * 8 + t4 * 2;
            __half2 lo = __floats2half2_rn(acc_o[ni][0] * invA, acc_o[ni][1] * invA);
            __half2 hi = __floats2half2_rn(acc_o[ni][2] * invB, acc_o[ni][3] * invB);
            *(__half2*)(O + (size_t)rowA * DDIM + cc) = lo;
            *(__half2*)(O + (size_t)rowB * DDIM + cc) = hi;
        }
    }
}

// ---------------------------------------------------------------------------
extern "C" void kernel_launch(void* const* d_in, const int* in_sizes, int n_in,
                              void* d_out, int out_size)
{
    const float* x    = (const float*)d_in[0];
    const float* Wdq  = (const float*)d_in[1];
    const float* Wuq  = (const float*)d_in[2];
    const float* qg   = (const float*)d_in[3];
    const float* qb   = (const float*)d_in[4];
    const float* Wdkv = (const float*)d_in[5];
    const float* Wukv = (const float*)d_in[6];
    const float* kvg  = (const float*)d_in[7];
    const float* kvb  = (const float*)d_in[8];
    const float* Wo   = (const float*)d_in[9];
    float* out = (float*)d_out;

    float *c12, *Qb2, *KVb;
    __half *c12h, *Oh, *xh, *Wt12, *Wt3, *Wt4, *Woh;
    cudaGetSymbolAddress((void**)&c12,  g_c12);
    cudaGetSymbolAddress((void**)&c12h, g_c12h);
    cudaGetSymbolAddress((void**)&Qb2,  g_Q);
    cudaGetSymbolAddress((void**)&KVb,  g_KV);
    cudaGetSymbolAddress((void**)&Oh,   g_Oh);
    cudaGetSymbolAddress((void**)&xh,   g_xh);
    cudaGetSymbolAddress((void**)&Wt12, g_Wt12);
    cudaGetSymbolAddress((void**)&Wt3,  g_Wt3);
    cudaGetSymbolAddress((void**)&Wt4,  g_Wt4);
    cudaGetSymbolAddress((void**)&Woh,  g_Woh);

    cudaFuncSetAttribute(attn_mma_kernel, cudaFuncAttributeMaxDynamicSharedMemorySize,
                         ATTN_SMEM_BYTES);
    cudaFuncSetAttribute(hgemm_mma, cudaFuncAttributeMaxDynamicSharedMemorySize,
                         HG_SMEM);

    dim3 tb(32, 8);
    transpose_kernel<<<dim3(64,  64), tb>>>(Wdq,  Wt12, DDIM, DDIM);
    transpose_kernel<<<dim3(64,  64), tb>>>(Wdkv, Wt12 + (size_t)DDIM * DDIM,
                                            DDIM, DDIM);
    transpose_kernel<<<dim3(64,  64), tb>>>(Wuq,  Wt3, DDIM, DDIM);
    transpose_kernel<<<dim3(128, 64), tb>>>(Wukv, Wt4, DDIM, 2 * DDIM);
    half_kernel<<<(BS_ROWS * DDIM / 4 + 255) / 256, 256>>>(x,  xh, BS_ROWS * DDIM / 4);
    half_kernel<<<(DDIM * DDIM / 4 + 255) / 256, 256>>>(Wo, Woh, DDIM * DDIM / 4);

    dim3 blk(256);

    hgemm_mma<<<dim3(16, 32), blk, HG_SMEM>>>(xh, DDIM, Wt12, DDIM,
                                              c12, 2 * DDIM,
                                              BS_ROWS, 2 * DDIM, DDIM);

    float* ckv_out = (out_size >= 2 * BS_ROWS * DDIM)
                         ? (out + (size_t)BS_ROWS * DDIM) : nullptr;
    ln2_kernel<<<dim3(BS_ROWS, 2), 256>>>(c12, c12h, qg, qb, kvg, kvb, ckv_out);

    hgemm_mma<<<dim3(8, 32),  blk, HG_SMEM>>>(c12h,        2 * DDIM, Wt3, DDIM,
                                              Qb2, DDIM, BS_ROWS, DDIM, DDIM);
    hgemm_mma<<<dim3(16, 32), blk, HG_SMEM>>>(c12h + DDIM, 2 * DDIM, Wt4, DDIM,
                                              KVb, 2 * DDIM, BS_ROWS, 2 * DDIM, DDIM);

    rope_kernel<<<BS_ROWS, 1024>>>(Qb2, KVb);

    attn_mma_kernel<<<dim3(32, HDIM, BDIM), blk, ATTN_SMEM_BYTES>>>(Qb2, KVb, Oh);

    hgemm_mma<<<dim3(8, 32), blk, HG_SMEM>>>(Oh, DDIM, Woh, DDIM,
                                             out, DDIM, BS_ROWS, DDIM, DDIM);
}